// round 1
// baseline (speedup 1.0000x reference)
#include <cuda_runtime.h>
#include <math.h>

#define Bsz   4
#define Sseq  2048
#define Dm    768
#define Hh    16
#define DHh   48
#define NROWS (Bsz * Sseq)

// Scratch (allocation-free rule: __device__ globals)
__device__ float g_Q[NROWS * Dm];
__device__ float g_K[NROWS * Dm];
__device__ float g_V[NROWS * Dm];
__device__ float g_O[NROWS * Dm];

// ---------------------------------------------------------------------------
// GEMM: Y[M,N] = X[M,K] @ W[K,N] + bias[N].  M=8192, N=K=768.
// 128x128 block tile, BK=8, 256 threads, 8x8 per-thread micro-tile.
// ---------------------------------------------------------------------------
__global__ __launch_bounds__(256) void gemm_bias_kernel(
    const float* __restrict__ X, const float* __restrict__ W,
    const float* __restrict__ bias, float* __restrict__ Y)
{
    const int M = NROWS, N = Dm, K = Dm;
    __shared__ float As[8][128];
    __shared__ float Bs[8][128];

    int tid = threadIdx.x;
    int bm = blockIdx.y * 128;
    int bn = blockIdx.x * 128;

    int arow = tid >> 1;            // 0..127
    int acol = (tid & 1) * 4;       // 0 or 4
    int brow = tid >> 5;            // 0..7
    int bcol = (tid & 31) * 4;      // 0..124

    const float* Xp = X + (size_t)(bm + arow) * K + acol;
    const float* Wp = W + (size_t)brow * N + bn + bcol;

    int tx = tid & 15, ty = tid >> 4;

    float acc[8][8];
#pragma unroll
    for (int i = 0; i < 8; i++)
#pragma unroll
        for (int j = 0; j < 8; j++) acc[i][j] = 0.f;

    for (int k0 = 0; k0 < K; k0 += 8) {
        float4 a4 = *(const float4*)(Xp + k0);
        float4 b4 = *(const float4*)(Wp + (size_t)k0 * N);
        As[acol + 0][arow] = a4.x;
        As[acol + 1][arow] = a4.y;
        As[acol + 2][arow] = a4.z;
        As[acol + 3][arow] = a4.w;
        *(float4*)&Bs[brow][bcol] = b4;
        __syncthreads();

#pragma unroll
        for (int kk = 0; kk < 8; kk++) {
            float a[8], b[8];
            *(float4*)(a)     = *(float4*)&As[kk][ty * 8];
            *(float4*)(a + 4) = *(float4*)&As[kk][ty * 8 + 4];
            *(float4*)(b)     = *(float4*)&Bs[kk][tx * 8];
            *(float4*)(b + 4) = *(float4*)&Bs[kk][tx * 8 + 4];
#pragma unroll
            for (int i = 0; i < 8; i++)
#pragma unroll
                for (int j = 0; j < 8; j++)
                    acc[i][j] += a[i] * b[j];
        }
        __syncthreads();
    }

#pragma unroll
    for (int i = 0; i < 8; i++) {
        int row = bm + ty * 8 + i;
#pragma unroll
        for (int j = 0; j < 8; j += 4) {
            int col = bn + tx * 8 + j;
            float4 o;
            o.x = acc[i][j + 0] + bias[col + 0];
            o.y = acc[i][j + 1] + bias[col + 1];
            o.z = acc[i][j + 2] + bias[col + 2];
            o.w = acc[i][j + 3] + bias[col + 3];
            *(float4*)&Y[(size_t)row * N + col] = o;
        }
    }
}

// ---------------------------------------------------------------------------
// Causal flash attention. One block per (q-tile of 64 rows, b*h).
// 256 threads; tx=0..15 (key cols / DH cols), ty=0..15 (query rows).
// Each thread: 4x4 score tile, O accumulators 4 rows x 3 DH-cols.
// ---------------------------------------------------------------------------
__global__ __launch_bounds__(256) void attn_kernel(
    const float* __restrict__ Qg, const float* __restrict__ Kg,
    const float* __restrict__ Vg, float* __restrict__ Og)
{
    extern __shared__ float sm[];
    float* Qs = sm;                      // [64][48]
    float* Ks = Qs + 64 * 48;            // [64][49]  (pad to break conflicts)
    float* Vs = Ks + 64 * 49;            // [64][48]
    float* Ss = Vs + 64 * 48;            // [64][65]

    const float scale = 0.14433756729740643f; // 1/sqrt(48)

    int qt = blockIdx.x;       // 0..31
    int bh = blockIdx.y;       // 0..63
    int b = bh >> 4, h = bh & 15;
    int tid = threadIdx.x;
    int tx = tid & 15, ty = tid >> 4;
    int rowbase = b * Sseq;
    int q0 = qt * 64;
    int hoff = h * DHh;

    // Load Q tile
    for (int idx = tid; idx < 64 * 48; idx += 256) {
        int r = idx / 48, c = idx - r * 48;
        Qs[idx] = Qg[(size_t)(rowbase + q0 + r) * Dm + hoff + c];
    }

    float m_i[4], l_i[4], o[4][3];
#pragma unroll
    for (int r = 0; r < 4; r++) {
        m_i[r] = -INFINITY;
        l_i[r] = 0.f;
        o[r][0] = o[r][1] = o[r][2] = 0.f;
    }

    for (int j = 0; j <= qt; j++) {
        int k0 = j * 64;
        __syncthreads();   // protects Qs (first iter) and Ks/Vs/Ss reuse
        for (int idx = tid; idx < 64 * 48; idx += 256) {
            int r = idx / 48, c = idx - r * 48;
            size_t g = (size_t)(rowbase + k0 + r) * Dm + hoff + c;
            Ks[r * 49 + c] = Kg[g];
            Vs[idx]        = Vg[g];
        }
        __syncthreads();

        // S = Q K^T for this 4x4 micro-tile
        float s[4][4];
#pragma unroll
        for (int r = 0; r < 4; r++)
#pragma unroll
            for (int c = 0; c < 4; c++) s[r][c] = 0.f;

#pragma unroll 8
        for (int kk = 0; kk < 48; kk++) {
            float qv[4], kv[4];
#pragma unroll
            for (int r = 0; r < 4; r++) qv[r] = Qs[(ty * 4 + r) * 48 + kk];
#pragma unroll
            for (int c = 0; c < 4; c++) kv[c] = Ks[(tx * 4 + c) * 49 + kk];
#pragma unroll
            for (int r = 0; r < 4; r++)
#pragma unroll
                for (int c = 0; c < 4; c++)
                    s[r][c] += qv[r] * kv[c];
        }

        bool diag = (j == qt);
#pragma unroll
        for (int r = 0; r < 4; r++) {
            int qidx = q0 + ty * 4 + r;
#pragma unroll
            for (int c = 0; c < 4; c++) {
                s[r][c] *= scale;
                if (diag && qidx < k0 + tx * 4 + c) s[r][c] = -INFINITY;
            }
        }

        // Online softmax per row; row spread over the 16 tx lanes (same warp half)
#pragma unroll
        for (int r = 0; r < 4; r++) {
            float mx = fmaxf(fmaxf(s[r][0], s[r][1]), fmaxf(s[r][2], s[r][3]));
#pragma unroll
            for (int off = 1; off < 16; off <<= 1)
                mx = fmaxf(mx, __shfl_xor_sync(0xffffffffu, mx, off));
            float mnew = fmaxf(m_i[r], mx);
            float alpha = __expf(m_i[r] - mnew);
            float p[4], psum = 0.f;
#pragma unroll
            for (int c = 0; c < 4; c++) {
                p[c] = __expf(s[r][c] - mnew);
                psum += p[c];
            }
#pragma unroll
            for (int off = 1; off < 16; off <<= 1)
                psum += __shfl_xor_sync(0xffffffffu, psum, off);
            l_i[r] = l_i[r] * alpha + psum;
            m_i[r] = mnew;
#pragma unroll
            for (int c = 0; c < 4; c++)
                Ss[(ty * 4 + r) * 65 + tx * 4 + c] = p[c];
            o[r][0] *= alpha; o[r][1] *= alpha; o[r][2] *= alpha;
        }
        __syncthreads();

        // O += P @ V   (thread owns rows ty*4..+3, DH cols tx*3..+2)
#pragma unroll 4
        for (int kk = 0; kk < 64; kk++) {
            float v0 = Vs[kk * 48 + tx * 3 + 0];
            float v1 = Vs[kk * 48 + tx * 3 + 1];
            float v2 = Vs[kk * 48 + tx * 3 + 2];
#pragma unroll
            for (int r = 0; r < 4; r++) {
                float p = Ss[(ty * 4 + r) * 65 + kk];
                o[r][0] += p * v0;
                o[r][1] += p * v1;
                o[r][2] += p * v2;
            }
        }
    }

    // Write out (normalize by l)
#pragma unroll
    for (int r = 0; r < 4; r++) {
        float inv = 1.f / l_i[r];
        size_t base = (size_t)(rowbase + q0 + ty * 4 + r) * Dm + hoff + tx * 3;
        Og[base + 0] = o[r][0] * inv;
        Og[base + 1] = o[r][1] * inv;
        Og[base + 2] = o[r][2] * inv;
    }
}

// ---------------------------------------------------------------------------
// LayerNorm over last dim (768). One block per row, 256 threads, 3 elems each.
// ---------------------------------------------------------------------------
__global__ __launch_bounds__(256) void ln_kernel(
    const float* __restrict__ X, const float* __restrict__ gamma,
    const float* __restrict__ beta, float* __restrict__ Y)
{
    int row = blockIdx.x;
    int tid = threadIdx.x;
    const float* x = X + (size_t)row * Dm;

    float v0 = x[tid], v1 = x[tid + 256], v2 = x[tid + 512];
    float s  = v0 + v1 + v2;
    float sq = v0 * v0 + v1 * v1 + v2 * v2;

#pragma unroll
    for (int off = 16; off > 0; off >>= 1) {
        s  += __shfl_xor_sync(0xffffffffu, s, off);
        sq += __shfl_xor_sync(0xffffffffu, sq, off);
    }
    __shared__ float red_s[8], red_q[8];
    int wid = tid >> 5, lid = tid & 31;
    if (lid == 0) { red_s[wid] = s; red_q[wid] = sq; }
    __syncthreads();
    if (wid == 0) {
        float a = (lid < 8) ? red_s[lid] : 0.f;
        float b = (lid < 8) ? red_q[lid] : 0.f;
#pragma unroll
        for (int off = 4; off > 0; off >>= 1) {
            a += __shfl_xor_sync(0xffffffffu, a, off);
            b += __shfl_xor_sync(0xffffffffu, b, off);
        }
        if (lid == 0) { red_s[0] = a; red_q[0] = b; }
    }
    __syncthreads();
    float mu  = red_s[0] * (1.f / Dm);
    float var = red_q[0] * (1.f / Dm) - mu * mu;
    float inv = rsqrtf(var + 1e-3f);

    float* y = Y + (size_t)row * Dm;
    y[tid]       = (v0 - mu) * inv * gamma[tid]       + beta[tid];
    y[tid + 256] = (v1 - mu) * inv * gamma[tid + 256] + beta[tid + 256];
    y[tid + 512] = (v2 - mu) * inv * gamma[tid + 512] + beta[tid + 512];
}

// ---------------------------------------------------------------------------
extern "C" void kernel_launch(void* const* d_in, const int* in_sizes, int n_in,
                              void* d_out, int out_size)
{
    const float* q     = (const float*)d_in[0];
    const float* k     = (const float*)d_in[1];
    const float* v     = (const float*)d_in[2];
    const float* Wq    = (const float*)d_in[3];
    const float* bq    = (const float*)d_in[4];
    const float* Wk    = (const float*)d_in[5];
    const float* bk    = (const float*)d_in[6];
    const float* Wv    = (const float*)d_in[7];
    const float* bv    = (const float*)d_in[8];
    const float* gamma = (const float*)d_in[9];
    const float* beta  = (const float*)d_in[10];
    float* out = (float*)d_out;

    float *Qg, *Kg, *Vg, *Og;
    cudaGetSymbolAddress((void**)&Qg, g_Q);
    cudaGetSymbolAddress((void**)&Kg, g_K);
    cudaGetSymbolAddress((void**)&Vg, g_V);
    cudaGetSymbolAddress((void**)&Og, g_O);

    dim3 ggrid(Dm / 128, NROWS / 128);   // (6, 64)
    gemm_bias_kernel<<<ggrid, 256>>>(q, Wq, bq, Qg);
    gemm_bias_kernel<<<ggrid, 256>>>(k, Wk, bk, Kg);
    gemm_bias_kernel<<<ggrid, 256>>>(v, Wv, bv, Vg);

    size_t smem = (size_t)(64 * 48 + 64 * 49 + 64 * 48 + 64 * 65) * sizeof(float);
    cudaFuncSetAttribute(attn_kernel, cudaFuncAttributeMaxDynamicSharedMemorySize, (int)smem);
    attn_kernel<<<dim3(Sseq / 64, Bsz * Hh), 256, smem>>>(Qg, Kg, Vg, Og);

    ln_kernel<<<NROWS, 256>>>(Og, gamma, beta, out);
}

// round 3
// speedup vs baseline: 1.2555x; 1.2555x over previous
#include <cuda_runtime.h>
#include <cuda_bf16.h>
#include <mma.h>
#include <math.h>
#include <stdint.h>

using namespace nvcuda;

#define Bsz   4
#define Sseq  2048
#define Dm    768
#define Hh    16
#define DHh   48
#define NROWS (Bsz * Sseq)

// Scratch (allocation-free rule: __device__ globals)
__device__ float g_Q[NROWS * Dm];
__device__ float g_K[NROWS * Dm];
__device__ float g_V[NROWS * Dm];
__device__ float g_O[NROWS * Dm];
// bf16 split operands (reused across the three projections)
__device__ __nv_bfloat16 g_Xhi[NROWS * Dm];
__device__ __nv_bfloat16 g_Xlo[NROWS * Dm];
__device__ __nv_bfloat16 g_Wthi[Dm * Dm];   // transposed: [n][k]
__device__ __nv_bfloat16 g_Wtlo[Dm * Dm];

// ============================ converters ===================================
__global__ __launch_bounds__(256) void convert_x_kernel(
    const float* __restrict__ X, __nv_bfloat16* __restrict__ hi,
    __nv_bfloat16* __restrict__ lo)
{
    int idx = (blockIdx.x * 256 + threadIdx.x) * 4;
    float4 v = *(const float4*)(X + idx);
    __nv_bfloat16 h0 = __float2bfloat16_rn(v.x);
    __nv_bfloat16 h1 = __float2bfloat16_rn(v.y);
    __nv_bfloat16 h2 = __float2bfloat16_rn(v.z);
    __nv_bfloat16 h3 = __float2bfloat16_rn(v.w);
    __nv_bfloat16 l0 = __float2bfloat16_rn(v.x - __bfloat162float(h0));
    __nv_bfloat16 l1 = __float2bfloat16_rn(v.y - __bfloat162float(h1));
    __nv_bfloat16 l2 = __float2bfloat16_rn(v.z - __bfloat162float(h2));
    __nv_bfloat16 l3 = __float2bfloat16_rn(v.w - __bfloat162float(h3));
    __nv_bfloat162 hp0 = __nv_bfloat162(h0, h1), hp1 = __nv_bfloat162(h2, h3);
    __nv_bfloat162 lp0 = __nv_bfloat162(l0, l1), lp1 = __nv_bfloat162(l2, l3);
    uint2 hu, lu;
    hu.x = *(uint32_t*)&hp0; hu.y = *(uint32_t*)&hp1;
    lu.x = *(uint32_t*)&lp0; lu.y = *(uint32_t*)&lp1;
    *(uint2*)(hi + idx) = hu;
    *(uint2*)(lo + idx) = lu;
}

// Transpose + split: Out[n][k] = split(W[k][n])
__global__ __launch_bounds__(256) void convert_w_kernel(
    const float* __restrict__ W, __nv_bfloat16* __restrict__ hi,
    __nv_bfloat16* __restrict__ lo)
{
    __shared__ float tile[32][33];
    int tx = threadIdx.x, ty = threadIdx.y;
    int bx = blockIdx.x, by = blockIdx.y;
#pragma unroll
    for (int i = 0; i < 4; i++) {
        int k = by * 32 + ty + i * 8;
        int n = bx * 32 + tx;
        tile[ty + i * 8][tx] = W[k * Dm + n];
    }
    __syncthreads();
#pragma unroll
    for (int i = 0; i < 4; i++) {
        int n = bx * 32 + ty + i * 8;
        int k = by * 32 + tx;
        float v = tile[tx][ty + i * 8];
        __nv_bfloat16 h = __float2bfloat16_rn(v);
        __nv_bfloat16 l = __float2bfloat16_rn(v - __bfloat162float(h));
        hi[n * Dm + k] = h;
        lo[n * Dm + k] = l;
    }
}

// ============================ wmma GEMM ====================================
// Y[M=8192, N=768] = X @ W + bias via split-3 bf16 (Ah*Bh + Ah*Bl + Al*Bh).
// Block tile 64(M) x 128(N), BK=32, 8 warps (2x4), warp tile 32x32.
#define BK    32
#define LDT   40                       // 32 + 8 pad (80B rows: conflict-free)
#define NCHK  (Dm / BK)                // 24
// smem layout (bf16 elements):
//   sA[buf][part][64*LDT]   : 2*2*2560 = 10240 elems = 20480 B
//   sB[buf][part][128*LDT]  : 2*2*5120 = 20480 elems = 40960 B
#define SA_OFF(buf, part) (((buf) * 2 + (part)) * 64 * LDT)
#define SB_OFF(buf, part) (10240 + ((buf) * 2 + (part)) * 128 * LDT)
#define GEMM_SMEM_BYTES (61440)

__global__ __launch_bounds__(256) void gemm_wmma_kernel(
    const __nv_bfloat16* __restrict__ Ahi, const __nv_bfloat16* __restrict__ Alo,
    const __nv_bfloat16* __restrict__ Bhi, const __nv_bfloat16* __restrict__ Blo,
    const float* __restrict__ bias, float* __restrict__ Y)
{
    extern __shared__ __align__(128) __nv_bfloat16 sm[];
    int tid = threadIdx.x;
    int w   = tid >> 5;
    int bm  = blockIdx.y * 64;
    int bn  = blockIdx.x * 128;

    // Warp tile origin
    int wm = (w >> 2) * 32;        // 0 or 32
    int wn = (w & 3) * 32;         // 0..96

    wmma::fragment<wmma::accumulator, 16, 16, 16, float> acc[2][2];
#pragma unroll
    for (int i = 0; i < 2; i++)
#pragma unroll
        for (int j = 0; j < 2; j++) wmma::fill_fragment(acc[i][j], 0.f);

    // Loader indices: A part: 64 rows x 4 segs (of 8 bf16) = 256 -> 1 seg/thread
    int ar = tid >> 2, as = (tid & 3) * 8;
    // B part: 128 rows x 4 segs = 512 -> 2 segs/thread
    int br0 = tid >> 1, bs0 = (tid & 1) * 16;   // two adjacent segs of 8 => 16 elems

    const __nv_bfloat16* gAh = Ahi + (size_t)(bm + ar) * Dm + as;
    const __nv_bfloat16* gAl = Alo + (size_t)(bm + ar) * Dm + as;
    const __nv_bfloat16* gBh = Bhi + (size_t)(bn + br0) * Dm + bs0;
    const __nv_bfloat16* gBl = Blo + (size_t)(bn + br0) * Dm + bs0;

    // Prologue: load chunk 0 into buf 0
    {
        float4 vah = *(const float4*)(gAh);
        float4 val = *(const float4*)(gAl);
        float4 vbh0 = *(const float4*)(gBh);
        float4 vbh1 = *(const float4*)(gBh + 8);
        float4 vbl0 = *(const float4*)(gBl);
        float4 vbl1 = *(const float4*)(gBl + 8);
        *(float4*)(sm + SA_OFF(0,0) + ar * LDT + as) = vah;
        *(float4*)(sm + SA_OFF(0,1) + ar * LDT + as) = val;
        *(float4*)(sm + SB_OFF(0,0) + br0 * LDT + bs0) = vbh0;
        *(float4*)(sm + SB_OFF(0,0) + br0 * LDT + bs0 + 8) = vbh1;
        *(float4*)(sm + SB_OFF(0,1) + br0 * LDT + bs0) = vbl0;
        *(float4*)(sm + SB_OFF(0,1) + br0 * LDT + bs0 + 8) = vbl1;
    }
    __syncthreads();

    for (int c = 0; c < NCHK; c++) {
        int buf = c & 1;
        // Issue global loads for next chunk first (latency overlap)
        float4 vah, val, vbh0, vbh1, vbl0, vbl1;
        if (c + 1 < NCHK) {
            int k0 = (c + 1) * BK;
            vah  = *(const float4*)(gAh + k0);
            val  = *(const float4*)(gAl + k0);
            vbh0 = *(const float4*)(gBh + k0);
            vbh1 = *(const float4*)(gBh + k0 + 8);
            vbl0 = *(const float4*)(gBl + k0);
            vbl1 = *(const float4*)(gBl + k0 + 8);
        }

        // Compute on current buffer
        const __nv_bfloat16* pAh = sm + SA_OFF(buf,0);
        const __nv_bfloat16* pAl = sm + SA_OFF(buf,1);
        const __nv_bfloat16* pBh = sm + SB_OFF(buf,0);
        const __nv_bfloat16* pBl = sm + SB_OFF(buf,1);
#pragma unroll
        for (int ks = 0; ks < BK / 16; ks++) {
            wmma::fragment<wmma::matrix_a, 16, 16, 16, __nv_bfloat16, wmma::row_major> ah[2], al[2];
            wmma::fragment<wmma::matrix_b, 16, 16, 16, __nv_bfloat16, wmma::col_major> bh[2], bl[2];
#pragma unroll
            for (int i = 0; i < 2; i++) {
                wmma::load_matrix_sync(ah[i], pAh + (wm + i * 16) * LDT + ks * 16, LDT);
                wmma::load_matrix_sync(al[i], pAl + (wm + i * 16) * LDT + ks * 16, LDT);
            }
#pragma unroll
            for (int j = 0; j < 2; j++) {
                wmma::load_matrix_sync(bh[j], pBh + (wn + j * 16) * LDT + ks * 16, LDT);
                wmma::load_matrix_sync(bl[j], pBl + (wn + j * 16) * LDT + ks * 16, LDT);
            }
#pragma unroll
            for (int i = 0; i < 2; i++)
#pragma unroll
                for (int j = 0; j < 2; j++) {
                    wmma::mma_sync(acc[i][j], ah[i], bh[j], acc[i][j]);
                    wmma::mma_sync(acc[i][j], ah[i], bl[j], acc[i][j]);
                    wmma::mma_sync(acc[i][j], al[i], bh[j], acc[i][j]);
                }
        }

        // Stage next chunk
        if (c + 1 < NCHK) {
            int nb = buf ^ 1;
            *(float4*)(sm + SA_OFF(nb,0) + ar * LDT + as) = vah;
            *(float4*)(sm + SA_OFF(nb,1) + ar * LDT + as) = val;
            *(float4*)(sm + SB_OFF(nb,0) + br0 * LDT + bs0) = vbh0;
            *(float4*)(sm + SB_OFF(nb,0) + br0 * LDT + bs0 + 8) = vbh1;
            *(float4*)(sm + SB_OFF(nb,1) + br0 * LDT + bs0) = vbl0;
            *(float4*)(sm + SB_OFF(nb,1) + br0 * LDT + bs0 + 8) = vbl1;
        }
        __syncthreads();
    }

    // Epilogue: fragments -> smem staging (64x128 f32 = 32KB), bias add, store
    float* sOut = (float*)sm;
#pragma unroll
    for (int i = 0; i < 2; i++)
#pragma unroll
        for (int j = 0; j < 2; j++)
            wmma::store_matrix_sync(sOut + (wm + i * 16) * 128 + wn + j * 16,
                                    acc[i][j], 128, wmma::mem_row_major);
    __syncthreads();

#pragma unroll
    for (int it = 0; it < 8; it++) {
        int idx = tid + it * 256;          // over 2048 float4 slots
        int row = idx >> 5, c4 = (idx & 31) * 4;
        float4 o = *(float4*)(sOut + row * 128 + c4);
        const float* bp = bias + bn + c4;
        o.x += bp[0]; o.y += bp[1]; o.z += bp[2]; o.w += bp[3];
        *(float4*)(Y + (size_t)(bm + row) * Dm + bn + c4) = o;
    }
}

// ---------------------------------------------------------------------------
// Causal flash attention (fp32, unchanged from R1).
// ---------------------------------------------------------------------------
__global__ __launch_bounds__(256) void attn_kernel(
    const float* __restrict__ Qg, const float* __restrict__ Kg,
    const float* __restrict__ Vg, float* __restrict__ Og)
{
    extern __shared__ float smf[];
    float* Qs = smf;
    float* Ks = Qs + 64 * 48;
    float* Vs = Ks + 64 * 49;
    float* Ss = Vs + 64 * 48;

    const float scale = 0.14433756729740643f;

    int qt = blockIdx.x;
    int bh = blockIdx.y;
    int b = bh >> 4, h = bh & 15;
    int tid = threadIdx.x;
    int tx = tid & 15, ty = tid >> 4;
    int rowbase = b * Sseq;
    int q0 = qt * 64;
    int hoff = h * DHh;

    for (int idx = tid; idx < 64 * 48; idx += 256) {
        int r = idx / 48, c = idx - r * 48;
        Qs[idx] = Qg[(size_t)(rowbase + q0 + r) * Dm + hoff + c];
    }

    float m_i[4], l_i[4], o[4][3];
#pragma unroll
    for (int r = 0; r < 4; r++) {
        m_i[r] = -INFINITY; l_i[r] = 0.f;
        o[r][0] = o[r][1] = o[r][2] = 0.f;
    }

    for (int j = 0; j <= qt; j++) {
        int k0 = j * 64;
        __syncthreads();
        for (int idx = tid; idx < 64 * 48; idx += 256) {
            int r = idx / 48, c = idx - r * 48;
            size_t g = (size_t)(rowbase + k0 + r) * Dm + hoff + c;
            Ks[r * 49 + c] = Kg[g];
            Vs[idx]        = Vg[g];
        }
        __syncthreads();

        float s[4][4];
#pragma unroll
        for (int r = 0; r < 4; r++)
#pragma unroll
            for (int c = 0; c < 4; c++) s[r][c] = 0.f;

#pragma unroll 8
        for (int kk = 0; kk < 48; kk++) {
            float qv[4], kv[4];
#pragma unroll
            for (int r = 0; r < 4; r++) qv[r] = Qs[(ty * 4 + r) * 48 + kk];
#pragma unroll
            for (int c = 0; c < 4; c++) kv[c] = Ks[(tx * 4 + c) * 49 + kk];
#pragma unroll
            for (int r = 0; r < 4; r++)
#pragma unroll
                for (int c = 0; c < 4; c++)
                    s[r][c] += qv[r] * kv[c];
        }

        bool diag = (j == qt);
#pragma unroll
        for (int r = 0; r < 4; r++) {
            int qidx = q0 + ty * 4 + r;
#pragma unroll
            for (int c = 0; c < 4; c++) {
                s[r][c] *= scale;
                if (diag && qidx < k0 + tx * 4 + c) s[r][c] = -INFINITY;
            }
        }

#pragma unroll
        for (int r = 0; r < 4; r++) {
            float mx = fmaxf(fmaxf(s[r][0], s[r][1]), fmaxf(s[r][2], s[r][3]));
#pragma unroll
            for (int off = 1; off < 16; off <<= 1)
                mx = fmaxf(mx, __shfl_xor_sync(0xffffffffu, mx, off));
            float mnew = fmaxf(m_i[r], mx);
            float alpha = __expf(m_i[r] - mnew);
            float p[4], psum = 0.f;
#pragma unroll
            for (int c = 0; c < 4; c++) {
                p[c] = __expf(s[r][c] - mnew);
                psum += p[c];
            }
#pragma unroll
            for (int off = 1; off < 16; off <<= 1)
                psum += __shfl_xor_sync(0xffffffffu, psum, off);
            l_i[r] = l_i[r] * alpha + psum;
            m_i[r] = mnew;
#pragma unroll
            for (int c = 0; c < 4; c++)
                Ss[(ty * 4 + r) * 65 + tx * 4 + c] = p[c];
            o[r][0] *= alpha; o[r][1] *= alpha; o[r][2] *= alpha;
        }
        __syncthreads();

#pragma unroll 4
        for (int kk = 0; kk < 64; kk++) {
            float v0 = Vs[kk * 48 + tx * 3 + 0];
            float v1 = Vs[kk * 48 + tx * 3 + 1];
            float v2 = Vs[kk * 48 + tx * 3 + 2];
#pragma unroll
            for (int r = 0; r < 4; r++) {
                float p = Ss[(ty * 4 + r) * 65 + kk];
                o[r][0] += p * v0;
                o[r][1] += p * v1;
                o[r][2] += p * v2;
            }
        }
    }

#pragma unroll
    for (int r = 0; r < 4; r++) {
        float inv = 1.f / l_i[r];
        size_t base = (size_t)(rowbase + q0 + ty * 4 + r) * Dm + hoff + tx * 3;
        Og[base + 0] = o[r][0] * inv;
        Og[base + 1] = o[r][1] * inv;
        Og[base + 2] = o[r][2] * inv;
    }
}

// ---------------------------------------------------------------------------
// LayerNorm (unchanged)
// ---------------------------------------------------------------------------
__global__ __launch_bounds__(256) void ln_kernel(
    const float* __restrict__ X, const float* __restrict__ gamma,
    const float* __restrict__ beta, float* __restrict__ Y)
{
    int row = blockIdx.x;
    int tid = threadIdx.x;
    const float* x = X + (size_t)row * Dm;

    float v0 = x[tid], v1 = x[tid + 256], v2 = x[tid + 512];
    float s  = v0 + v1 + v2;
    float sq = v0 * v0 + v1 * v1 + v2 * v2;

#pragma unroll
    for (int off = 16; off > 0; off >>= 1) {
        s  += __shfl_xor_sync(0xffffffffu, s, off);
        sq += __shfl_xor_sync(0xffffffffu, sq, off);
    }
    __shared__ float red_s[8], red_q[8];
    int wid = tid >> 5, lid = tid & 31;
    if (lid == 0) { red_s[wid] = s; red_q[wid] = sq; }
    __syncthreads();
    if (wid == 0) {
        float a = (lid < 8) ? red_s[lid] : 0.f;
        float b = (lid < 8) ? red_q[lid] : 0.f;
#pragma unroll
        for (int off = 4; off > 0; off >>= 1) {
            a += __shfl_xor_sync(0xffffffffu, a, off);
            b += __shfl_xor_sync(0xffffffffu, b, off);
        }
        if (lid == 0) { red_s[0] = a; red_q[0] = b; }
    }
    __syncthreads();
    float mu  = red_s[0] * (1.f / Dm);
    float var = red_q[0] * (1.f / Dm) - mu * mu;
    float inv = rsqrtf(var + 1e-3f);

    float* y = Y + (size_t)row * Dm;
    y[tid]       = (v0 - mu) * inv * gamma[tid]       + beta[tid];
    y[tid + 256] = (v1 - mu) * inv * gamma[tid + 256] + beta[tid + 256];
    y[tid + 512] = (v2 - mu) * inv * gamma[tid + 512] + beta[tid + 512];
}

// ---------------------------------------------------------------------------
extern "C" void kernel_launch(void* const* d_in, const int* in_sizes, int n_in,
                              void* d_out, int out_size)
{
    const float* q     = (const float*)d_in[0];
    const float* k     = (const float*)d_in[1];
    const float* v     = (const float*)d_in[2];
    const float* Wq    = (const float*)d_in[3];
    const float* bq    = (const float*)d_in[4];
    const float* Wk    = (const float*)d_in[5];
    const float* bk    = (const float*)d_in[6];
    const float* Wv    = (const float*)d_in[7];
    const float* bv    = (const float*)d_in[8];
    const float* gamma = (const float*)d_in[9];
    const float* beta  = (const float*)d_in[10];
    float* out = (float*)d_out;

    float *Qg, *Kg, *Vg, *Og;
    __nv_bfloat16 *xhi, *xlo, *whi, *wlo;
    cudaGetSymbolAddress((void**)&Qg, g_Q);
    cudaGetSymbolAddress((void**)&Kg, g_K);
    cudaGetSymbolAddress((void**)&Vg, g_V);
    cudaGetSymbolAddress((void**)&Og, g_O);
    cudaGetSymbolAddress((void**)&xhi, g_Xhi);
    cudaGetSymbolAddress((void**)&xlo, g_Xlo);
    cudaGetSymbolAddress((void**)&whi, g_Wthi);
    cudaGetSymbolAddress((void**)&wlo, g_Wtlo);

    cudaFuncSetAttribute(gemm_wmma_kernel, cudaFuncAttributeMaxDynamicSharedMemorySize,
                         GEMM_SMEM_BYTES);

    dim3 cxgrid(NROWS * Dm / (256 * 4));
    dim3 cwgrid(Dm / 32, Dm / 32);
    dim3 cwblk(32, 8);
    dim3 ggrid(Dm / 128, NROWS / 64);   // (6, 128)

    const float* Xs[3] = {q, k, v};
    const float* Ws[3] = {Wq, Wk, Wv};
    const float* bs[3] = {bq, bk, bv};
    float* Ys[3] = {Qg, Kg, Vg};
    for (int i = 0; i < 3; i++) {
        convert_x_kernel<<<cxgrid, 256>>>(Xs[i], xhi, xlo);
        convert_w_kernel<<<cwgrid, cwblk>>>(Ws[i], whi, wlo);
        gemm_wmma_kernel<<<ggrid, 256, GEMM_SMEM_BYTES>>>(xhi, xlo, whi, wlo, bs[i], Ys[i]);
    }

    size_t smem = (size_t)(64 * 48 + 64 * 49 + 64 * 48 + 64 * 65) * sizeof(float);
    cudaFuncSetAttribute(attn_kernel, cudaFuncAttributeMaxDynamicSharedMemorySize, (int)smem);
    attn_kernel<<<dim3(Sseq / 64, Bsz * Hh), 256, smem>>>(Qg, Kg, Vg, Og);

    ln_kernel<<<NROWS, 256>>>(Og, gamma, beta, out);
}

// round 4
// speedup vs baseline: 1.3041x; 1.0387x over previous
#include <cuda_runtime.h>
#include <cuda_bf16.h>
#include <mma.h>
#include <math.h>
#include <stdint.h>

using namespace nvcuda;

#define Bsz   4
#define Sseq  2048
#define Dm    768
#define Hh    16
#define DHh   48
#define NROWS (Bsz * Sseq)

// softmax scale (1/sqrt(48)) * log2(e): folded into Q projection; exp2f in softmax
#define QSCALE 0.2082351f

// Scratch (__device__ globals per allocation-free rule)
__device__ float g_O[NROWS * Dm];
__device__ __nv_bfloat16 g_Xhi[NROWS * Dm];
__device__ __nv_bfloat16 g_Xlo[NROWS * Dm];
__device__ __nv_bfloat16 g_Wthi[Dm * Dm];   // transposed: [n][k]
__device__ __nv_bfloat16 g_Wtlo[Dm * Dm];
__device__ __nv_bfloat16 g_Qhi[NROWS * Dm];
__device__ __nv_bfloat16 g_Qlo[NROWS * Dm];
__device__ __nv_bfloat16 g_Khi[NROWS * Dm];
__device__ __nv_bfloat16 g_Klo[NROWS * Dm];
__device__ __nv_bfloat16 g_Vhi[NROWS * Dm];
__device__ __nv_bfloat16 g_Vlo[NROWS * Dm];

// ============================ converters ===================================
__global__ __launch_bounds__(256) void convert_x_kernel(
    const float* __restrict__ X, __nv_bfloat16* __restrict__ hi,
    __nv_bfloat16* __restrict__ lo)
{
    int idx = (blockIdx.x * 256 + threadIdx.x) * 4;
    float4 v = *(const float4*)(X + idx);
    __nv_bfloat16 h0 = __float2bfloat16_rn(v.x);
    __nv_bfloat16 h1 = __float2bfloat16_rn(v.y);
    __nv_bfloat16 h2 = __float2bfloat16_rn(v.z);
    __nv_bfloat16 h3 = __float2bfloat16_rn(v.w);
    __nv_bfloat16 l0 = __float2bfloat16_rn(v.x - __bfloat162float(h0));
    __nv_bfloat16 l1 = __float2bfloat16_rn(v.y - __bfloat162float(h1));
    __nv_bfloat16 l2 = __float2bfloat16_rn(v.z - __bfloat162float(h2));
    __nv_bfloat16 l3 = __float2bfloat16_rn(v.w - __bfloat162float(h3));
    __nv_bfloat162 hp0 = __nv_bfloat162(h0, h1), hp1 = __nv_bfloat162(h2, h3);
    __nv_bfloat162 lp0 = __nv_bfloat162(l0, l1), lp1 = __nv_bfloat162(l2, l3);
    uint2 hu, lu;
    hu.x = *(uint32_t*)&hp0; hu.y = *(uint32_t*)&hp1;
    lu.x = *(uint32_t*)&lp0; lu.y = *(uint32_t*)&lp1;
    *(uint2*)(hi + idx) = hu;
    *(uint2*)(lo + idx) = lu;
}

// Transpose + split: Out[n][k] = split(W[k][n])
__global__ __launch_bounds__(256) void convert_w_kernel(
    const float* __restrict__ W, __nv_bfloat16* __restrict__ hi,
    __nv_bfloat16* __restrict__ lo)
{
    __shared__ float tile[32][33];
    int tx = threadIdx.x, ty = threadIdx.y;
    int bx = blockIdx.x, by = blockIdx.y;
#pragma unroll
    for (int i = 0; i < 4; i++) {
        int k = by * 32 + ty + i * 8;
        int n = bx * 32 + tx;
        tile[ty + i * 8][tx] = W[k * Dm + n];
    }
    __syncthreads();
#pragma unroll
    for (int i = 0; i < 4; i++) {
        int n = bx * 32 + ty + i * 8;
        int k = by * 32 + tx;
        float v = tile[tx][ty + i * 8];
        __nv_bfloat16 h = __float2bfloat16_rn(v);
        __nv_bfloat16 l = __float2bfloat16_rn(v - __bfloat162float(h));
        hi[n * Dm + k] = h;
        lo[n * Dm + k] = l;
    }
}

// ============================ wmma GEMM ====================================
// Y = (X @ W + bias) * scale, emitted as split bf16 (hi, lo).
// Block tile 64(M) x 128(N), BK=32, 8 warps (2x4), warp tile 32x32.
#define BK    32
#define LDT   40
#define NCHK  (Dm / BK)                // 24
#define SA_OFF(buf, part) (((buf) * 2 + (part)) * 64 * LDT)
#define SB_OFF(buf, part) (10240 + ((buf) * 2 + (part)) * 128 * LDT)
#define GEMM_SMEM_BYTES (61440)

__global__ __launch_bounds__(256) void gemm_wmma_kernel(
    const __nv_bfloat16* __restrict__ Ahi, const __nv_bfloat16* __restrict__ Alo,
    const __nv_bfloat16* __restrict__ Bhi, const __nv_bfloat16* __restrict__ Blo,
    const float* __restrict__ bias, __nv_bfloat16* __restrict__ Yhi,
    __nv_bfloat16* __restrict__ Ylo, float scale)
{
    extern __shared__ __align__(128) __nv_bfloat16 sm[];
    int tid = threadIdx.x;
    int w   = tid >> 5;
    int bm  = blockIdx.y * 64;
    int bn  = blockIdx.x * 128;

    int wm = (w >> 2) * 32;
    int wn = (w & 3) * 32;

    wmma::fragment<wmma::accumulator, 16, 16, 16, float> acc[2][2];
#pragma unroll
    for (int i = 0; i < 2; i++)
#pragma unroll
        for (int j = 0; j < 2; j++) wmma::fill_fragment(acc[i][j], 0.f);

    int ar = tid >> 2, as = (tid & 3) * 8;
    int br0 = tid >> 1, bs0 = (tid & 1) * 16;

    const __nv_bfloat16* gAh = Ahi + (size_t)(bm + ar) * Dm + as;
    const __nv_bfloat16* gAl = Alo + (size_t)(bm + ar) * Dm + as;
    const __nv_bfloat16* gBh = Bhi + (size_t)(bn + br0) * Dm + bs0;
    const __nv_bfloat16* gBl = Blo + (size_t)(bn + br0) * Dm + bs0;

    {
        float4 vah = *(const float4*)(gAh);
        float4 val = *(const float4*)(gAl);
        float4 vbh0 = *(const float4*)(gBh);
        float4 vbh1 = *(const float4*)(gBh + 8);
        float4 vbl0 = *(const float4*)(gBl);
        float4 vbl1 = *(const float4*)(gBl + 8);
        *(float4*)(sm + SA_OFF(0,0) + ar * LDT + as) = vah;
        *(float4*)(sm + SA_OFF(0,1) + ar * LDT + as) = val;
        *(float4*)(sm + SB_OFF(0,0) + br0 * LDT + bs0) = vbh0;
        *(float4*)(sm + SB_OFF(0,0) + br0 * LDT + bs0 + 8) = vbh1;
        *(float4*)(sm + SB_OFF(0,1) + br0 * LDT + bs0) = vbl0;
        *(float4*)(sm + SB_OFF(0,1) + br0 * LDT + bs0 + 8) = vbl1;
    }
    __syncthreads();

    for (int c = 0; c < NCHK; c++) {
        int buf = c & 1;
        float4 vah, val, vbh0, vbh1, vbl0, vbl1;
        if (c + 1 < NCHK) {
            int k0 = (c + 1) * BK;
            vah  = *(const float4*)(gAh + k0);
            val  = *(const float4*)(gAl + k0);
            vbh0 = *(const float4*)(gBh + k0);
            vbh1 = *(const float4*)(gBh + k0 + 8);
            vbl0 = *(const float4*)(gBl + k0);
            vbl1 = *(const float4*)(gBl + k0 + 8);
        }

        const __nv_bfloat16* pAh = sm + SA_OFF(buf,0);
        const __nv_bfloat16* pAl = sm + SA_OFF(buf,1);
        const __nv_bfloat16* pBh = sm + SB_OFF(buf,0);
        const __nv_bfloat16* pBl = sm + SB_OFF(buf,1);
#pragma unroll
        for (int ks = 0; ks < BK / 16; ks++) {
            wmma::fragment<wmma::matrix_a, 16, 16, 16, __nv_bfloat16, wmma::row_major> ah[2], al[2];
            wmma::fragment<wmma::matrix_b, 16, 16, 16, __nv_bfloat16, wmma::col_major> bh[2], bl[2];
#pragma unroll
            for (int i = 0; i < 2; i++) {
                wmma::load_matrix_sync(ah[i], pAh + (wm + i * 16) * LDT + ks * 16, LDT);
                wmma::load_matrix_sync(al[i], pAl + (wm + i * 16) * LDT + ks * 16, LDT);
            }
#pragma unroll
            for (int j = 0; j < 2; j++) {
                wmma::load_matrix_sync(bh[j], pBh + (wn + j * 16) * LDT + ks * 16, LDT);
                wmma::load_matrix_sync(bl[j], pBl + (wn + j * 16) * LDT + ks * 16, LDT);
            }
#pragma unroll
            for (int i = 0; i < 2; i++)
#pragma unroll
                for (int j = 0; j < 2; j++) {
                    wmma::mma_sync(acc[i][j], ah[i], bh[j], acc[i][j]);
                    wmma::mma_sync(acc[i][j], ah[i], bl[j], acc[i][j]);
                    wmma::mma_sync(acc[i][j], al[i], bh[j], acc[i][j]);
                }
        }

        if (c + 1 < NCHK) {
            int nb = buf ^ 1;
            *(float4*)(sm + SA_OFF(nb,0) + ar * LDT + as) = vah;
            *(float4*)(sm + SA_OFF(nb,1) + ar * LDT + as) = val;
            *(float4*)(sm + SB_OFF(nb,0) + br0 * LDT + bs0) = vbh0;
            *(float4*)(sm + SB_OFF(nb,0) + br0 * LDT + bs0 + 8) = vbh1;
            *(float4*)(sm + SB_OFF(nb,1) + br0 * LDT + bs0) = vbl0;
            *(float4*)(sm + SB_OFF(nb,1) + br0 * LDT + bs0 + 8) = vbl1;
        }
        __syncthreads();
    }

    float* sOut = (float*)sm;
#pragma unroll
    for (int i = 0; i < 2; i++)
#pragma unroll
        for (int j = 0; j < 2; j++)
            wmma::store_matrix_sync(sOut + (wm + i * 16) * 128 + wn + j * 16,
                                    acc[i][j], 128, wmma::mem_row_major);
    __syncthreads();

#pragma unroll
    for (int it = 0; it < 8; it++) {
        int idx = tid + it * 256;
        int row = idx >> 5, c4 = (idx & 31) * 4;
        float4 o = *(float4*)(sOut + row * 128 + c4);
        const float* bp = bias + bn + c4;
        float y0 = (o.x + bp[0]) * scale;
        float y1 = (o.y + bp[1]) * scale;
        float y2 = (o.z + bp[2]) * scale;
        float y3 = (o.w + bp[3]) * scale;
        __nv_bfloat16 h0 = __float2bfloat16_rn(y0);
        __nv_bfloat16 h1 = __float2bfloat16_rn(y1);
        __nv_bfloat16 h2 = __float2bfloat16_rn(y2);
        __nv_bfloat16 h3 = __float2bfloat16_rn(y3);
        __nv_bfloat16 l0 = __float2bfloat16_rn(y0 - __bfloat162float(h0));
        __nv_bfloat16 l1 = __float2bfloat16_rn(y1 - __bfloat162float(h1));
        __nv_bfloat16 l2 = __float2bfloat16_rn(y2 - __bfloat162float(h2));
        __nv_bfloat16 l3 = __float2bfloat16_rn(y3 - __bfloat162float(h3));
        __nv_bfloat162 hp0 = __nv_bfloat162(h0, h1), hp1 = __nv_bfloat162(h2, h3);
        __nv_bfloat162 lp0 = __nv_bfloat162(l0, l1), lp1 = __nv_bfloat162(l2, l3);
        uint2 hu, lu;
        hu.x = *(uint32_t*)&hp0; hu.y = *(uint32_t*)&hp1;
        lu.x = *(uint32_t*)&lp0; lu.y = *(uint32_t*)&lp1;
        size_t off = (size_t)(bm + row) * Dm + bn + c4;
        *(uint2*)(Yhi + off) = hu;
        *(uint2*)(Ylo + off) = lu;
    }
}

// ============================ tensor-core flash attention ===================
// Block: 128 q-rows x (k-tiles of 64). 8 warps; warp = 16-row strip.
// smem layout (bytes):
//   Qh 0        : 128x56 bf16 = 14336
//   Ql 14336    : 14336
//   Kh 28672    : 64x56 bf16 = 7168
//   Kl 35840    : 7168
//   Vh 43008    : 7168
//   Vl 50176    : 7168
//   Sf 57344    : 128x68 f32 = 34816   (aliased: S scores, then PV result)
//   Ph 92160    : 128x72 bf16 = 18432
//   Pl 110592   : 18432
// total 129024
#define ATTN_SMEM 129024
#define LDQ 56
#define LDS_S 68
#define LDP 72

__global__ __launch_bounds__(256) void attn_tc_kernel(
    const __nv_bfloat16* __restrict__ Qh_g, const __nv_bfloat16* __restrict__ Ql_g,
    const __nv_bfloat16* __restrict__ Kh_g, const __nv_bfloat16* __restrict__ Kl_g,
    const __nv_bfloat16* __restrict__ Vh_g, const __nv_bfloat16* __restrict__ Vl_g,
    float* __restrict__ Og)
{
    extern __shared__ __align__(128) char smraw[];
    __nv_bfloat16* Qh = (__nv_bfloat16*)(smraw);
    __nv_bfloat16* Ql = (__nv_bfloat16*)(smraw + 14336);
    __nv_bfloat16* Kh = (__nv_bfloat16*)(smraw + 28672);
    __nv_bfloat16* Kl = (__nv_bfloat16*)(smraw + 35840);
    __nv_bfloat16* Vh = (__nv_bfloat16*)(smraw + 43008);
    __nv_bfloat16* Vl = (__nv_bfloat16*)(smraw + 50176);
    float*         Sf = (float*)(smraw + 57344);
    __nv_bfloat16* Ph = (__nv_bfloat16*)(smraw + 92160);
    __nv_bfloat16* Pl = (__nv_bfloat16*)(smraw + 110592);

    int qt = (int)gridDim.x - 1 - (int)blockIdx.x;   // big tiles first
    int bh = blockIdx.y;
    int b = bh >> 4, h = bh & 15;
    int tid = threadIdx.x;
    int w = tid >> 5;
    int rowbase = b * Sseq;
    int q0 = qt * 128;
    int hoff = h * DHh;

    // Load Q tile (both parts): 2 arrays x 128 rows x 6 segs(8 bf16) = 1536
    for (int s = tid; s < 1536; s += 256) {
        int arr = s / 768;
        int r = (s % 768) / 6;
        int c8 = (s % 6) * 8;
        const __nv_bfloat16* src = (arr ? Ql_g : Qh_g) +
            (size_t)(rowbase + q0 + r) * Dm + hoff + c8;
        __nv_bfloat16* dst = (arr ? Ql : Qh) + r * LDQ + c8;
        *(uint4*)dst = *(const uint4*)src;
    }

    int row = tid >> 1;          // 0..127
    int half = tid & 1;          // 0/1: softmax cols [half*32,+32), O cols [half*24,+24)
    float m_i = -1e30f, l_i = 0.f;
    float o_acc[24];
#pragma unroll
    for (int c = 0; c < 24; c++) o_acc[c] = 0.f;

    int ntiles = 2 * qt + 2;
    for (int j = 0; j < ntiles; j++) {
        int k0 = j * 64;
        __syncthreads();   // prior-iter smem reads done before overwrite
        // Load K/V tiles: 4 arrays x 64 rows x 6 segs = 1536
        for (int s = tid; s < 1536; s += 256) {
            int arr = s / 384;
            int r = (s % 384) / 6;
            int c8 = (s % 6) * 8;
            const __nv_bfloat16* src;
            __nv_bfloat16* dst;
            switch (arr) {
                case 0: src = Kh_g; dst = Kh; break;
                case 1: src = Kl_g; dst = Kl; break;
                case 2: src = Vh_g; dst = Vh; break;
                default: src = Vl_g; dst = Vl; break;
            }
            *(uint4*)(dst + r * LDQ + c8) =
                *(const uint4*)(src + (size_t)(rowbase + k0 + r) * Dm + hoff + c8);
        }
        __syncthreads();

        // ---- S = Q K^T (split-3), warp strip of 16 rows x 64 cols ----
        {
            wmma::fragment<wmma::accumulator, 16, 16, 16, float> accS[4];
#pragma unroll
            for (int n = 0; n < 4; n++) wmma::fill_fragment(accS[n], 0.f);
#pragma unroll
            for (int ks = 0; ks < 3; ks++) {
                wmma::fragment<wmma::matrix_a, 16, 16, 16, __nv_bfloat16, wmma::row_major> fah, fal;
                wmma::load_matrix_sync(fah, Qh + (w * 16) * LDQ + ks * 16, LDQ);
                wmma::load_matrix_sync(fal, Ql + (w * 16) * LDQ + ks * 16, LDQ);
#pragma unroll
                for (int n = 0; n < 4; n++) {
                    wmma::fragment<wmma::matrix_b, 16, 16, 16, __nv_bfloat16, wmma::col_major> fbh, fbl;
                    wmma::load_matrix_sync(fbh, Kh + (n * 16) * LDQ + ks * 16, LDQ);
                    wmma::load_matrix_sync(fbl, Kl + (n * 16) * LDQ + ks * 16, LDQ);
                    wmma::mma_sync(accS[n], fah, fbh, accS[n]);
                    wmma::mma_sync(accS[n], fah, fbl, accS[n]);
                    wmma::mma_sync(accS[n], fal, fbh, accS[n]);
                }
            }
#pragma unroll
            for (int n = 0; n < 4; n++)
                wmma::store_matrix_sync(Sf + (w * 16) * LDS_S + n * 16, accS[n],
                                        LDS_S, wmma::mem_row_major);
        }
        __syncthreads();

        // ---- softmax (base-2 logits; scale folded into Q) ----
        float alpha;
        {
            bool need_mask = (j >= 2 * qt);
            int qg = q0 + row;
            float sv[32];
            const float* srow = Sf + row * LDS_S + half * 32;
#pragma unroll
            for (int i = 0; i < 8; i++)
                *(float4*)(sv + i * 4) = *(const float4*)(srow + i * 4);
            if (need_mask) {
                int cbase = k0 + half * 32;
#pragma unroll
                for (int i = 0; i < 32; i++)
                    if (qg < cbase + i) sv[i] = -1e30f;
            }
            float mx = -1e30f;
#pragma unroll
            for (int i = 0; i < 32; i++) mx = fmaxf(mx, sv[i]);
            mx = fmaxf(mx, __shfl_xor_sync(0xffffffffu, mx, 1));
            float mnew = fmaxf(m_i, mx);
            alpha = exp2f(m_i - mnew);
            float psum = 0.f;
#pragma unroll
            for (int i = 0; i < 32; i++) {
                sv[i] = exp2f(sv[i] - mnew);
                psum += sv[i];
            }
            psum += __shfl_xor_sync(0xffffffffu, psum, 1);
            l_i = l_i * alpha + psum;
            m_i = mnew;
            // write P split bf16
            __nv_bfloat16* ph = Ph + row * LDP + half * 32;
            __nv_bfloat16* pl = Pl + row * LDP + half * 32;
#pragma unroll
            for (int i = 0; i < 16; i++) {
                float p0 = sv[2 * i], p1 = sv[2 * i + 1];
                __nv_bfloat16 h0 = __float2bfloat16_rn(p0);
                __nv_bfloat16 h1 = __float2bfloat16_rn(p1);
                __nv_bfloat16 l0 = __float2bfloat16_rn(p0 - __bfloat162float(h0));
                __nv_bfloat16 l1 = __float2bfloat16_rn(p1 - __bfloat162float(h1));
                __nv_bfloat162 hp = __nv_bfloat162(h0, h1);
                __nv_bfloat162 lp = __nv_bfloat162(l0, l1);
                *(uint32_t*)(ph + 2 * i) = *(uint32_t*)&hp;
                *(uint32_t*)(pl + 2 * i) = *(uint32_t*)&lp;
            }
        }
        __syncthreads();

        // ---- PV = P @ V (split-3), result into Sf (aliased) ----
        {
            wmma::fragment<wmma::accumulator, 16, 16, 16, float> accO[3];
#pragma unroll
            for (int n = 0; n < 3; n++) wmma::fill_fragment(accO[n], 0.f);
#pragma unroll
            for (int ks = 0; ks < 4; ks++) {
                wmma::fragment<wmma::matrix_a, 16, 16, 16, __nv_bfloat16, wmma::row_major> fph, fpl;
                wmma::load_matrix_sync(fph, Ph + (w * 16) * LDP + ks * 16, LDP);
                wmma::load_matrix_sync(fpl, Pl + (w * 16) * LDP + ks * 16, LDP);
#pragma unroll
                for (int n = 0; n < 3; n++) {
                    wmma::fragment<wmma::matrix_b, 16, 16, 16, __nv_bfloat16, wmma::row_major> fvh, fvl;
                    wmma::load_matrix_sync(fvh, Vh + (ks * 16) * LDQ + n * 16, LDQ);
                    wmma::load_matrix_sync(fvl, Vl + (ks * 16) * LDQ + n * 16, LDQ);
                    wmma::mma_sync(accO[n], fph, fvh, accO[n]);
                    wmma::mma_sync(accO[n], fph, fvl, accO[n]);
                    wmma::mma_sync(accO[n], fpl, fvh, accO[n]);
                }
            }
#pragma unroll
            for (int n = 0; n < 3; n++)
                wmma::store_matrix_sync(Sf + (w * 16) * LDS_S + n * 16, accO[n],
                                        LDS_S, wmma::mem_row_major);
        }
        __syncthreads();

        // ---- merge: O = O*alpha + PV ----
        {
            const float* pv = Sf + row * LDS_S + half * 24;
#pragma unroll
            for (int i = 0; i < 6; i++) {
                float4 t = *(const float4*)(pv + i * 4);
                o_acc[i * 4 + 0] = o_acc[i * 4 + 0] * alpha + t.x;
                o_acc[i * 4 + 1] = o_acc[i * 4 + 1] * alpha + t.y;
                o_acc[i * 4 + 2] = o_acc[i * 4 + 2] * alpha + t.z;
                o_acc[i * 4 + 3] = o_acc[i * 4 + 3] * alpha + t.w;
            }
        }
    }

    // Epilogue: normalize and write fp32 O
    float inv = 1.f / l_i;
    float* op = Og + (size_t)(rowbase + q0 + row) * Dm + hoff + half * 24;
#pragma unroll
    for (int i = 0; i < 6; i++) {
        float4 t;
        t.x = o_acc[i * 4 + 0] * inv;
        t.y = o_acc[i * 4 + 1] * inv;
        t.z = o_acc[i * 4 + 2] * inv;
        t.w = o_acc[i * 4 + 3] * inv;
        *(float4*)(op + i * 4) = t;
    }
}

// ---------------------------------------------------------------------------
// LayerNorm (unchanged)
// ---------------------------------------------------------------------------
__global__ __launch_bounds__(256) void ln_kernel(
    const float* __restrict__ X, const float* __restrict__ gamma,
    const float* __restrict__ beta, float* __restrict__ Y)
{
    int row = blockIdx.x;
    int tid = threadIdx.x;
    const float* x = X + (size_t)row * Dm;

    float v0 = x[tid], v1 = x[tid + 256], v2 = x[tid + 512];
    float s  = v0 + v1 + v2;
    float sq = v0 * v0 + v1 * v1 + v2 * v2;

#pragma unroll
    for (int off = 16; off > 0; off >>= 1) {
        s  += __shfl_xor_sync(0xffffffffu, s, off);
        sq += __shfl_xor_sync(0xffffffffu, sq, off);
    }
    __shared__ float red_s[8], red_q[8];
    int wid = tid >> 5, lid = tid & 31;
    if (lid == 0) { red_s[wid] = s; red_q[wid] = sq; }
    __syncthreads();
    if (wid == 0) {
        float a = (lid < 8) ? red_s[lid] : 0.f;
        float bq2 = (lid < 8) ? red_q[lid] : 0.f;
#pragma unroll
        for (int off = 4; off > 0; off >>= 1) {
            a += __shfl_xor_sync(0xffffffffu, a, off);
            bq2 += __shfl_xor_sync(0xffffffffu, bq2, off);
        }
        if (lid == 0) { red_s[0] = a; red_q[0] = bq2; }
    }
    __syncthreads();
    float mu  = red_s[0] * (1.f / Dm);
    float var = red_q[0] * (1.f / Dm) - mu * mu;
    float inv = rsqrtf(var + 1e-3f);

    float* y = Y + (size_t)row * Dm;
    y[tid]       = (v0 - mu) * inv * gamma[tid]       + beta[tid];
    y[tid + 256] = (v1 - mu) * inv * gamma[tid + 256] + beta[tid + 256];
    y[tid + 512] = (v2 - mu) * inv * gamma[tid + 512] + beta[tid + 512];
}

// ---------------------------------------------------------------------------
extern "C" void kernel_launch(void* const* d_in, const int* in_sizes, int n_in,
                              void* d_out, int out_size)
{
    const float* q     = (const float*)d_in[0];
    const float* k     = (const float*)d_in[1];
    const float* v     = (const float*)d_in[2];
    const float* Wq    = (const float*)d_in[3];
    const float* bq    = (const float*)d_in[4];
    const float* Wk    = (const float*)d_in[5];
    const float* bk    = (const float*)d_in[6];
    const float* Wv    = (const float*)d_in[7];
    const float* bv    = (const float*)d_in[8];
    const float* gamma = (const float*)d_in[9];
    const float* beta  = (const float*)d_in[10];
    float* out = (float*)d_out;

    float* Og;
    __nv_bfloat16 *xhi, *xlo, *whi, *wlo;
    __nv_bfloat16 *qhi, *qlo, *khi, *klo, *vhi, *vlo;
    cudaGetSymbolAddress((void**)&Og, g_O);
    cudaGetSymbolAddress((void**)&xhi, g_Xhi);
    cudaGetSymbolAddress((void**)&xlo, g_Xlo);
    cudaGetSymbolAddress((void**)&whi, g_Wthi);
    cudaGetSymbolAddress((void**)&wlo, g_Wtlo);
    cudaGetSymbolAddress((void**)&qhi, g_Qhi);
    cudaGetSymbolAddress((void**)&qlo, g_Qlo);
    cudaGetSymbolAddress((void**)&khi, g_Khi);
    cudaGetSymbolAddress((void**)&klo, g_Klo);
    cudaGetSymbolAddress((void**)&vhi, g_Vhi);
    cudaGetSymbolAddress((void**)&vlo, g_Vlo);

    cudaFuncSetAttribute(gemm_wmma_kernel, cudaFuncAttributeMaxDynamicSharedMemorySize,
                         GEMM_SMEM_BYTES);
    cudaFuncSetAttribute(attn_tc_kernel, cudaFuncAttributeMaxDynamicSharedMemorySize,
                         ATTN_SMEM);

    dim3 cxgrid(NROWS * Dm / (256 * 4));
    dim3 cwgrid(Dm / 32, Dm / 32);
    dim3 cwblk(32, 8);
    dim3 ggrid(Dm / 128, NROWS / 64);

    const float* Xs[3] = {q, k, v};
    const float* Ws[3] = {Wq, Wk, Wv};
    const float* bs[3] = {bq, bk, bv};
    __nv_bfloat16* Yhs[3] = {qhi, khi, vhi};
    __nv_bfloat16* Yls[3] = {qlo, klo, vlo};
    float scales[3] = {QSCALE, 1.0f, 1.0f};
    for (int i = 0; i < 3; i++) {
        convert_x_kernel<<<cxgrid, 256>>>(Xs[i], xhi, xlo);
        convert_w_kernel<<<cwgrid, cwblk>>>(Ws[i], whi, wlo);
        gemm_wmma_kernel<<<ggrid, 256, GEMM_SMEM_BYTES>>>(xhi, xlo, whi, wlo,
                                                          bs[i], Yhs[i], Yls[i], scales[i]);
    }

    attn_tc_kernel<<<dim3(Sseq / 128, Bsz * Hh), 256, ATTN_SMEM>>>(
        qhi, qlo, khi, klo, vhi, vlo, Og);

    ln_kernel<<<NROWS, 256>>>(Og, gamma, beta, out);
}

// round 5
// speedup vs baseline: 2.2507x; 1.7258x over previous
#include <cuda_runtime.h>
#include <cuda_bf16.h>
#include <mma.h>
#include <math.h>
#include <stdint.h>

using namespace nvcuda;

#define Bsz   4
#define Sseq  2048
#define Dm    768
#define Hh    16
#define DHh   48
#define NROWS (Bsz * Sseq)

// softmax scale (1/sqrt(48)) * log2(e): folded into Q projection; exp2 in softmax
#define QSCALE 0.2082351f

// Scratch (__device__ globals per allocation-free rule)
__device__ float g_O[NROWS * Dm];
__device__ __nv_bfloat16 g_Xhi[NROWS * Dm];
__device__ __nv_bfloat16 g_Xlo[NROWS * Dm];
__device__ __nv_bfloat16 g_Wthi[Dm * Dm];   // transposed: [n][k]
__device__ __nv_bfloat16 g_Wtlo[Dm * Dm];
__device__ __nv_bfloat16 g_Qhi[NROWS * Dm];
__device__ __nv_bfloat16 g_Qlo[NROWS * Dm];
__device__ __nv_bfloat16 g_Khi[NROWS * Dm];
__device__ __nv_bfloat16 g_Klo[NROWS * Dm];
__device__ __nv_bfloat16 g_Vhi[NROWS * Dm];
__device__ __nv_bfloat16 g_Vlo[NROWS * Dm];

// ============================ PTX helpers ==================================
__device__ __forceinline__ uint32_t smem_u32(const void* p) {
    uint32_t a;
    asm("{ .reg .u64 t; cvta.to.shared.u64 t, %1; cvt.u32.u64 %0, t; }" : "=r"(a) : "l"(p));
    return a;
}
__device__ __forceinline__ float ex2(float x) {
    float y; asm("ex2.approx.ftz.f32 %0, %1;" : "=f"(y) : "f"(x)); return y;
}
#define MMA16816(C, a0, a1, a2, a3, b0, b1)                                   \
    asm volatile("mma.sync.aligned.m16n8k16.row.col.f32.bf16.bf16.f32 "       \
        "{%0,%1,%2,%3}, {%4,%5,%6,%7}, {%8,%9}, {%0,%1,%2,%3};"               \
        : "+f"((C)[0]), "+f"((C)[1]), "+f"((C)[2]), "+f"((C)[3])              \
        : "r"(a0), "r"(a1), "r"(a2), "r"(a3), "r"(b0), "r"(b1))
#define LDSM_X4(r0, r1, r2, r3, addr)                                         \
    asm volatile("ldmatrix.sync.aligned.m8n8.x4.shared.b16 {%0,%1,%2,%3}, [%4];" \
        : "=r"(r0), "=r"(r1), "=r"(r2), "=r"(r3) : "r"(addr))
#define LDSM_X2(r0, r1, addr)                                                 \
    asm volatile("ldmatrix.sync.aligned.m8n8.x2.shared.b16 {%0,%1}, [%2];"    \
        : "=r"(r0), "=r"(r1) : "r"(addr))
#define LDSM_X2T(r0, r1, addr)                                                \
    asm volatile("ldmatrix.sync.aligned.m8n8.x2.trans.shared.b16 {%0,%1}, [%2];" \
        : "=r"(r0), "=r"(r1) : "r"(addr))
#define CP_ASYNC16(sa, ga)                                                    \
    asm volatile("cp.async.cg.shared.global [%0], [%1], 16;" :: "r"(sa), "l"(ga))
#define CP_COMMIT() asm volatile("cp.async.commit_group;" ::: "memory")
#define CP_WAIT1()  asm volatile("cp.async.wait_group 1;" ::: "memory")
#define CP_WAIT0()  asm volatile("cp.async.wait_group 0;" ::: "memory")

__device__ __forceinline__ uint32_t pack_split(float x, float y, uint32_t& lo) {
    __nv_bfloat16 hx = __float2bfloat16_rn(x);
    __nv_bfloat16 hy = __float2bfloat16_rn(y);
    __nv_bfloat16 lx = __float2bfloat16_rn(x - __bfloat162float(hx));
    __nv_bfloat16 ly = __float2bfloat16_rn(y - __bfloat162float(hy));
    __nv_bfloat162 h2(hx, hy), l2(lx, ly);
    lo = *(uint32_t*)&l2;
    return *(uint32_t*)&h2;
}

// ============================ converters ===================================
__global__ __launch_bounds__(256) void convert_x_kernel(
    const float* __restrict__ X, __nv_bfloat16* __restrict__ hi,
    __nv_bfloat16* __restrict__ lo)
{
    int idx = (blockIdx.x * 256 + threadIdx.x) * 4;
    float4 v = *(const float4*)(X + idx);
    __nv_bfloat16 h0 = __float2bfloat16_rn(v.x);
    __nv_bfloat16 h1 = __float2bfloat16_rn(v.y);
    __nv_bfloat16 h2 = __float2bfloat16_rn(v.z);
    __nv_bfloat16 h3 = __float2bfloat16_rn(v.w);
    __nv_bfloat16 l0 = __float2bfloat16_rn(v.x - __bfloat162float(h0));
    __nv_bfloat16 l1 = __float2bfloat16_rn(v.y - __bfloat162float(h1));
    __nv_bfloat16 l2 = __float2bfloat16_rn(v.z - __bfloat162float(h2));
    __nv_bfloat16 l3 = __float2bfloat16_rn(v.w - __bfloat162float(h3));
    __nv_bfloat162 hp0 = __nv_bfloat162(h0, h1), hp1 = __nv_bfloat162(h2, h3);
    __nv_bfloat162 lp0 = __nv_bfloat162(l0, l1), lp1 = __nv_bfloat162(l2, l3);
    uint2 hu, lu;
    hu.x = *(uint32_t*)&hp0; hu.y = *(uint32_t*)&hp1;
    lu.x = *(uint32_t*)&lp0; lu.y = *(uint32_t*)&lp1;
    *(uint2*)(hi + idx) = hu;
    *(uint2*)(lo + idx) = lu;
}

__global__ __launch_bounds__(256) void convert_w_kernel(
    const float* __restrict__ W, __nv_bfloat16* __restrict__ hi,
    __nv_bfloat16* __restrict__ lo)
{
    __shared__ float tile[32][33];
    int tx = threadIdx.x, ty = threadIdx.y;
    int bx = blockIdx.x, by = blockIdx.y;
#pragma unroll
    for (int i = 0; i < 4; i++) {
        int k = by * 32 + ty + i * 8;
        int n = bx * 32 + tx;
        tile[ty + i * 8][tx] = W[k * Dm + n];
    }
    __syncthreads();
#pragma unroll
    for (int i = 0; i < 4; i++) {
        int n = bx * 32 + ty + i * 8;
        int k = by * 32 + tx;
        float v = tile[tx][ty + i * 8];
        __nv_bfloat16 h = __float2bfloat16_rn(v);
        __nv_bfloat16 l = __float2bfloat16_rn(v - __bfloat162float(h));
        hi[n * Dm + k] = h;
        lo[n * Dm + k] = l;
    }
}

// ============================ wmma GEMM (unchanged, proven) ================
#define BK    32
#define LDT   40
#define NCHK  (Dm / BK)
#define SA_OFF(buf, part) (((buf) * 2 + (part)) * 64 * LDT)
#define SB_OFF(buf, part) (10240 + ((buf) * 2 + (part)) * 128 * LDT)
#define GEMM_SMEM_BYTES (61440)

__global__ __launch_bounds__(256) void gemm_wmma_kernel(
    const __nv_bfloat16* __restrict__ Ahi, const __nv_bfloat16* __restrict__ Alo,
    const __nv_bfloat16* __restrict__ Bhi, const __nv_bfloat16* __restrict__ Blo,
    const float* __restrict__ bias, __nv_bfloat16* __restrict__ Yhi,
    __nv_bfloat16* __restrict__ Ylo, float scale)
{
    extern __shared__ __align__(128) __nv_bfloat16 sm[];
    int tid = threadIdx.x;
    int w   = tid >> 5;
    int bm  = blockIdx.y * 64;
    int bn  = blockIdx.x * 128;

    int wm = (w >> 2) * 32;
    int wn = (w & 3) * 32;

    wmma::fragment<wmma::accumulator, 16, 16, 16, float> acc[2][2];
#pragma unroll
    for (int i = 0; i < 2; i++)
#pragma unroll
        for (int j = 0; j < 2; j++) wmma::fill_fragment(acc[i][j], 0.f);

    int ar = tid >> 2, as = (tid & 3) * 8;
    int br0 = tid >> 1, bs0 = (tid & 1) * 16;

    const __nv_bfloat16* gAh = Ahi + (size_t)(bm + ar) * Dm + as;
    const __nv_bfloat16* gAl = Alo + (size_t)(bm + ar) * Dm + as;
    const __nv_bfloat16* gBh = Bhi + (size_t)(bn + br0) * Dm + bs0;
    const __nv_bfloat16* gBl = Blo + (size_t)(bn + br0) * Dm + bs0;

    {
        float4 vah = *(const float4*)(gAh);
        float4 val = *(const float4*)(gAl);
        float4 vbh0 = *(const float4*)(gBh);
        float4 vbh1 = *(const float4*)(gBh + 8);
        float4 vbl0 = *(const float4*)(gBl);
        float4 vbl1 = *(const float4*)(gBl + 8);
        *(float4*)(sm + SA_OFF(0,0) + ar * LDT + as) = vah;
        *(float4*)(sm + SA_OFF(0,1) + ar * LDT + as) = val;
        *(float4*)(sm + SB_OFF(0,0) + br0 * LDT + bs0) = vbh0;
        *(float4*)(sm + SB_OFF(0,0) + br0 * LDT + bs0 + 8) = vbh1;
        *(float4*)(sm + SB_OFF(0,1) + br0 * LDT + bs0) = vbl0;
        *(float4*)(sm + SB_OFF(0,1) + br0 * LDT + bs0 + 8) = vbl1;
    }
    __syncthreads();

    for (int c = 0; c < NCHK; c++) {
        int buf = c & 1;
        float4 vah, val, vbh0, vbh1, vbl0, vbl1;
        if (c + 1 < NCHK) {
            int k0 = (c + 1) * BK;
            vah  = *(const float4*)(gAh + k0);
            val  = *(const float4*)(gAl + k0);
            vbh0 = *(const float4*)(gBh + k0);
            vbh1 = *(const float4*)(gBh + k0 + 8);
            vbl0 = *(const float4*)(gBl + k0);
            vbl1 = *(const float4*)(gBl + k0 + 8);
        }

        const __nv_bfloat16* pAh = sm + SA_OFF(buf,0);
        const __nv_bfloat16* pAl = sm + SA_OFF(buf,1);
        const __nv_bfloat16* pBh = sm + SB_OFF(buf,0);
        const __nv_bfloat16* pBl = sm + SB_OFF(buf,1);
#pragma unroll
        for (int ks = 0; ks < BK / 16; ks++) {
            wmma::fragment<wmma::matrix_a, 16, 16, 16, __nv_bfloat16, wmma::row_major> ah[2], al[2];
            wmma::fragment<wmma::matrix_b, 16, 16, 16, __nv_bfloat16, wmma::col_major> bh[2], bl[2];
#pragma unroll
            for (int i = 0; i < 2; i++) {
                wmma::load_matrix_sync(ah[i], pAh + (wm + i * 16) * LDT + ks * 16, LDT);
                wmma::load_matrix_sync(al[i], pAl + (wm + i * 16) * LDT + ks * 16, LDT);
            }
#pragma unroll
            for (int j = 0; j < 2; j++) {
                wmma::load_matrix_sync(bh[j], pBh + (wn + j * 16) * LDT + ks * 16, LDT);
                wmma::load_matrix_sync(bl[j], pBl + (wn + j * 16) * LDT + ks * 16, LDT);
            }
#pragma unroll
            for (int i = 0; i < 2; i++)
#pragma unroll
                for (int j = 0; j < 2; j++) {
                    wmma::mma_sync(acc[i][j], ah[i], bh[j], acc[i][j]);
                    wmma::mma_sync(acc[i][j], ah[i], bl[j], acc[i][j]);
                    wmma::mma_sync(acc[i][j], al[i], bh[j], acc[i][j]);
                }
        }

        if (c + 1 < NCHK) {
            int nb = buf ^ 1;
            *(float4*)(sm + SA_OFF(nb,0) + ar * LDT + as) = vah;
            *(float4*)(sm + SA_OFF(nb,1) + ar * LDT + as) = val;
            *(float4*)(sm + SB_OFF(nb,0) + br0 * LDT + bs0) = vbh0;
            *(float4*)(sm + SB_OFF(nb,0) + br0 * LDT + bs0 + 8) = vbh1;
            *(float4*)(sm + SB_OFF(nb,1) + br0 * LDT + bs0) = vbl0;
            *(float4*)(sm + SB_OFF(nb,1) + br0 * LDT + bs0 + 8) = vbl1;
        }
        __syncthreads();
    }

    float* sOut = (float*)sm;
#pragma unroll
    for (int i = 0; i < 2; i++)
#pragma unroll
        for (int j = 0; j < 2; j++)
            wmma::store_matrix_sync(sOut + (wm + i * 16) * 128 + wn + j * 16,
                                    acc[i][j], 128, wmma::mem_row_major);
    __syncthreads();

#pragma unroll
    for (int it = 0; it < 8; it++) {
        int idx = tid + it * 256;
        int row = idx >> 5, c4 = (idx & 31) * 4;
        float4 o = *(float4*)(sOut + row * 128 + c4);
        const float* bp = bias + bn + c4;
        float y0 = (o.x + bp[0]) * scale;
        float y1 = (o.y + bp[1]) * scale;
        float y2 = (o.z + bp[2]) * scale;
        float y3 = (o.w + bp[3]) * scale;
        __nv_bfloat16 h0 = __float2bfloat16_rn(y0);
        __nv_bfloat16 h1 = __float2bfloat16_rn(y1);
        __nv_bfloat16 h2 = __float2bfloat16_rn(y2);
        __nv_bfloat16 h3 = __float2bfloat16_rn(y3);
        __nv_bfloat16 l0 = __float2bfloat16_rn(y0 - __bfloat162float(h0));
        __nv_bfloat16 l1 = __float2bfloat16_rn(y1 - __bfloat162float(h1));
        __nv_bfloat16 l2 = __float2bfloat16_rn(y2 - __bfloat162float(h2));
        __nv_bfloat16 l3 = __float2bfloat16_rn(y3 - __bfloat162float(h3));
        __nv_bfloat162 hp0 = __nv_bfloat162(h0, h1), hp1 = __nv_bfloat162(h2, h3);
        __nv_bfloat162 lp0 = __nv_bfloat162(l0, l1), lp1 = __nv_bfloat162(l2, l3);
        uint2 hu, lu;
        hu.x = *(uint32_t*)&hp0; hu.y = *(uint32_t*)&hp1;
        lu.x = *(uint32_t*)&lp0; lu.y = *(uint32_t*)&lp1;
        size_t off = (size_t)(bm + row) * Dm + bn + c4;
        *(uint2*)(Yhi + off) = hu;
        *(uint2*)(Ylo + off) = lu;
    }
}

// ============== register-resident flash attention (mma.sync) ===============
// CTA: 128 q-rows, 8 warps (16 rows each). KV tiles of 64, cp.async 3-buf ring.
// smem: Qh[128x56] Ql[128x56] then 3 x { Kh,Kl,Vh,Vl : 64x56 bf16 }.
#define LDA 56                           // row stride in bf16 (112B: conflict-free)
#define QARR (128 * LDA * 2)             // 14336 B per Q array
#define KARR (64 * LDA * 2)              // 6272 B per K/V array
#define BUFB (4 * KARR)                  // 25088 B per ring slot
#define ATTN_SMEM (2 * QARR + 3 * BUFB)  // 103936 B

__global__ __launch_bounds__(256) void attn_reg_kernel(
    const __nv_bfloat16* __restrict__ Qh_g, const __nv_bfloat16* __restrict__ Ql_g,
    const __nv_bfloat16* __restrict__ Kh_g, const __nv_bfloat16* __restrict__ Kl_g,
    const __nv_bfloat16* __restrict__ Vh_g, const __nv_bfloat16* __restrict__ Vl_g,
    float* __restrict__ Og)
{
    extern __shared__ __align__(128) char smraw[];
    uint32_t smb = smem_u32(smraw);
    __nv_bfloat16* Qh = (__nv_bfloat16*)smraw;
    __nv_bfloat16* Ql = (__nv_bfloat16*)(smraw + QARR);

    int qt = (int)gridDim.x - 1 - (int)blockIdx.x;
    int bh = blockIdx.y;
    int b = bh >> 4, h = bh & 15;
    int tid = threadIdx.x;
    int w = tid >> 5, lane = tid & 31;
    int rowbase = b * Sseq;
    int q0 = qt * 128;
    int hoff = h * DHh;
    int ntiles = 2 * qt + 2;

    // --- issue KV tile 0 (ring slot 0) ---
    {
#pragma unroll
        for (int it = 0; it < 6; it++) {
            int s = tid + it * 256;
            int arr = s / 384, rem = s - arr * 384;
            int r = rem / 6, c16 = rem - r * 6;
            const __nv_bfloat16* src = (arr == 0) ? Kh_g : (arr == 1) ? Kl_g :
                                       (arr == 2) ? Vh_g : Vl_g;
            const __nv_bfloat16* ga = src + (size_t)(rowbase + r) * Dm + hoff + c16 * 8;
            uint32_t sa = smb + 2 * QARR + arr * KARR + r * (LDA * 2) + c16 * 16;
            CP_ASYNC16(sa, ga);
        }
        CP_COMMIT();
    }

    // --- load Q tile into smem (direct), then Q fragments ---
    for (int s = tid; s < 1536; s += 256) {
        int arr = s / 768;
        int rem = s - arr * 768;
        int r = rem / 6, c8 = (rem - r * 6) * 8;
        const __nv_bfloat16* src = (arr ? Ql_g : Qh_g) +
            (size_t)(rowbase + q0 + r) * Dm + hoff + c8;
        __nv_bfloat16* dst = (arr ? Ql : Qh) + r * LDA + c8;
        *(uint4*)dst = *(const uint4*)src;
    }
    __syncthreads();

    int mat = lane >> 3;
    int qrow_loc = ((mat & 1) << 3) + (lane & 7);
    int qcol8 = (mat >> 1) << 3;
    uint32_t qh[3][4], ql[3][4];
#pragma unroll
    for (int ks = 0; ks < 3; ks++) {
        uint32_t a = smb + ((w * 16 + qrow_loc) * LDA + ks * 16 + qcol8) * 2;
        LDSM_X4(qh[ks][0], qh[ks][1], qh[ks][2], qh[ks][3], a);
        LDSM_X4(ql[ks][0], ql[ks][1], ql[ks][2], ql[ks][3], a + QARR);
    }

    int g = lane >> 2, t4 = lane & 3;
    int lane16 = lane & 15;
    int krow_loc = lane16 & 7;
    int khalf = (lane16 >> 3) << 3;     // 0 or 8

    float m0 = -1e30f, m1 = -1e30f, l0 = 0.f, l1 = 0.f;
    float o[6][4];
#pragma unroll
    for (int on = 0; on < 6; on++)
#pragma unroll
        for (int e = 0; e < 4; e++) o[on][e] = 0.f;

    for (int j = 0; j < ntiles; j++) {
        // issue tile j+1 into ring slot (j+1)%3
        if (j + 1 < ntiles) {
            int k0n = (j + 1) * 64;
            uint32_t bb = smb + 2 * QARR + ((j + 1) % 3) * BUFB;
#pragma unroll
            for (int it = 0; it < 6; it++) {
                int s = tid + it * 256;
                int arr = s / 384, rem = s - arr * 384;
                int r = rem / 6, c16 = rem - r * 6;
                const __nv_bfloat16* src = (arr == 0) ? Kh_g : (arr == 1) ? Kl_g :
                                           (arr == 2) ? Vh_g : Vl_g;
                const __nv_bfloat16* ga = src + (size_t)(rowbase + k0n + r) * Dm + hoff + c16 * 8;
                uint32_t sa = bb + arr * KARR + r * (LDA * 2) + c16 * 16;
                CP_ASYNC16(sa, ga);
            }
            CP_COMMIT();
            CP_WAIT1();
        } else {
            CP_WAIT0();
        }
        __syncthreads();

        uint32_t bufb = smb + 2 * QARR + (j % 3) * BUFB;
        uint32_t bufKh = bufb, bufKl = bufb + KARR;
        uint32_t bufVh = bufb + 2 * KARR, bufVl = bufb + 3 * KARR;

        // ---- S = Q K^T (split-3), accumulators in registers ----
        float sc[8][4];
#pragma unroll
        for (int jn = 0; jn < 8; jn++) {
#pragma unroll
            for (int e = 0; e < 4; e++) sc[jn][e] = 0.f;
            uint32_t kbase = ((jn * 8 + krow_loc) * LDA + khalf) * 2;
#pragma unroll
            for (int ks = 0; ks < 3; ks++) {
                uint32_t kh0, kh1, kl0, kl1;
                LDSM_X2(kh0, kh1, bufKh + kbase + ks * 32);
                LDSM_X2(kl0, kl1, bufKl + kbase + ks * 32);
                MMA16816(sc[jn], qh[ks][0], qh[ks][1], qh[ks][2], qh[ks][3], kh0, kh1);
                MMA16816(sc[jn], qh[ks][0], qh[ks][1], qh[ks][2], qh[ks][3], kl0, kl1);
                MMA16816(sc[jn], ql[ks][0], ql[ks][1], ql[ks][2], ql[ks][3], kh0, kh1);
            }
        }

        // ---- causal mask (diagonal tiles only) ----
        int k0 = j * 64;
        if (j >= 2 * qt) {
            int qg0 = q0 + w * 16 + g;
#pragma unroll
            for (int jn = 0; jn < 8; jn++) {
                int c = k0 + jn * 8 + 2 * t4;
                if (qg0 < c)     sc[jn][0] = -1e30f;
                if (qg0 < c + 1) sc[jn][1] = -1e30f;
                if (qg0 + 8 < c)     sc[jn][2] = -1e30f;
                if (qg0 + 8 < c + 1) sc[jn][3] = -1e30f;
            }
        }

        // ---- register softmax ----
        float mx0 = -1e30f, mx1 = -1e30f;
#pragma unroll
        for (int jn = 0; jn < 8; jn++) {
            mx0 = fmaxf(mx0, fmaxf(sc[jn][0], sc[jn][1]));
            mx1 = fmaxf(mx1, fmaxf(sc[jn][2], sc[jn][3]));
        }
        mx0 = fmaxf(mx0, __shfl_xor_sync(0xffffffffu, mx0, 1));
        mx0 = fmaxf(mx0, __shfl_xor_sync(0xffffffffu, mx0, 2));
        mx1 = fmaxf(mx1, __shfl_xor_sync(0xffffffffu, mx1, 1));
        mx1 = fmaxf(mx1, __shfl_xor_sync(0xffffffffu, mx1, 2));
        float mn0 = fmaxf(m0, mx0), mn1 = fmaxf(m1, mx1);
        float al0 = ex2(m0 - mn0), al1 = ex2(m1 - mn1);
        m0 = mn0; m1 = mn1;
        float ps0 = 0.f, ps1 = 0.f;
#pragma unroll
        for (int jn = 0; jn < 8; jn++) {
            sc[jn][0] = ex2(sc[jn][0] - mn0);
            sc[jn][1] = ex2(sc[jn][1] - mn0);
            sc[jn][2] = ex2(sc[jn][2] - mn1);
            sc[jn][3] = ex2(sc[jn][3] - mn1);
            ps0 += sc[jn][0] + sc[jn][1];
            ps1 += sc[jn][2] + sc[jn][3];
        }
        ps0 += __shfl_xor_sync(0xffffffffu, ps0, 1);
        ps0 += __shfl_xor_sync(0xffffffffu, ps0, 2);
        ps1 += __shfl_xor_sync(0xffffffffu, ps1, 1);
        ps1 += __shfl_xor_sync(0xffffffffu, ps1, 2);
        l0 = l0 * al0 + ps0;
        l1 = l1 * al1 + ps1;

        // ---- rescale O, then O += P V (split-3) directly in registers ----
#pragma unroll
        for (int on = 0; on < 6; on++) {
            o[on][0] *= al0; o[on][1] *= al0;
            o[on][2] *= al1; o[on][3] *= al1;
        }
#pragma unroll
        for (int ks = 0; ks < 4; ks++) {
            uint32_t pa[4], pl[4];
            pa[0] = pack_split(sc[2*ks][0],   sc[2*ks][1],   pl[0]);
            pa[1] = pack_split(sc[2*ks][2],   sc[2*ks][3],   pl[1]);
            pa[2] = pack_split(sc[2*ks+1][0], sc[2*ks+1][1], pl[2]);
            pa[3] = pack_split(sc[2*ks+1][2], sc[2*ks+1][3], pl[3]);
            uint32_t vrow = ((ks * 16 + krow_loc + khalf) * LDA) * 2;
#pragma unroll
            for (int on = 0; on < 6; on++) {
                uint32_t vh0, vh1, vl0, vl1;
                LDSM_X2T(vh0, vh1, bufVh + vrow + on * 16);
                LDSM_X2T(vl0, vl1, bufVl + vrow + on * 16);
                MMA16816(o[on], pa[0], pa[1], pa[2], pa[3], vh0, vh1);
                MMA16816(o[on], pa[0], pa[1], pa[2], pa[3], vl0, vl1);
                MMA16816(o[on], pl[0], pl[1], pl[2], pl[3], vh0, vh1);
            }
        }
        __syncthreads();   // all warps done reading ring slot before reuse
    }

    // ---- epilogue ----
    float inv0 = 1.f / l0, inv1 = 1.f / l1;
    float* op0 = Og + (size_t)(rowbase + q0 + w * 16 + g) * Dm + hoff + 2 * t4;
    float* op1 = op0 + 8 * Dm;
#pragma unroll
    for (int on = 0; on < 6; on++) {
        float2 r0 = make_float2(o[on][0] * inv0, o[on][1] * inv0);
        float2 r1 = make_float2(o[on][2] * inv1, o[on][3] * inv1);
        *(float2*)(op0 + on * 8) = r0;
        *(float2*)(op1 + on * 8) = r1;
    }
}

// ---------------------------------------------------------------------------
// LayerNorm (unchanged)
// ---------------------------------------------------------------------------
__global__ __launch_bounds__(256) void ln_kernel(
    const float* __restrict__ X, const float* __restrict__ gamma,
    const float* __restrict__ beta, float* __restrict__ Y)
{
    int row = blockIdx.x;
    int tid = threadIdx.x;
    const float* x = X + (size_t)row * Dm;

    float v0 = x[tid], v1 = x[tid + 256], v2 = x[tid + 512];
    float s  = v0 + v1 + v2;
    float sq = v0 * v0 + v1 * v1 + v2 * v2;

#pragma unroll
    for (int off = 16; off > 0; off >>= 1) {
        s  += __shfl_xor_sync(0xffffffffu, s, off);
        sq += __shfl_xor_sync(0xffffffffu, sq, off);
    }
    __shared__ float red_s[8], red_q[8];
    int wid = tid >> 5, lid = tid & 31;
    if (lid == 0) { red_s[wid] = s; red_q[wid] = sq; }
    __syncthreads();
    if (wid == 0) {
        float a = (lid < 8) ? red_s[lid] : 0.f;
        float bq2 = (lid < 8) ? red_q[lid] : 0.f;
#pragma unroll
        for (int off = 4; off > 0; off >>= 1) {
            a += __shfl_xor_sync(0xffffffffu, a, off);
            bq2 += __shfl_xor_sync(0xffffffffu, bq2, off);
        }
        if (lid == 0) { red_s[0] = a; red_q[0] = bq2; }
    }
    __syncthreads();
    float mu  = red_s[0] * (1.f / Dm);
    float var = red_q[0] * (1.f / Dm) - mu * mu;
    float inv = rsqrtf(var + 1e-3f);

    float* y = Y + (size_t)row * Dm;
    y[tid]       = (v0 - mu) * inv * gamma[tid]       + beta[tid];
    y[tid + 256] = (v1 - mu) * inv * gamma[tid + 256] + beta[tid + 256];
    y[tid + 512] = (v2 - mu) * inv * gamma[tid + 512] + beta[tid + 512];
}

// ---------------------------------------------------------------------------
extern "C" void kernel_launch(void* const* d_in, const int* in_sizes, int n_in,
                              void* d_out, int out_size)
{
    const float* q     = (const float*)d_in[0];
    const float* k     = (const float*)d_in[1];
    const float* v     = (const float*)d_in[2];
    const float* Wq    = (const float*)d_in[3];
    const float* bq    = (const float*)d_in[4];
    const float* Wk    = (const float*)d_in[5];
    const float* bk    = (const float*)d_in[6];
    const float* Wv    = (const float*)d_in[7];
    const float* bv    = (const float*)d_in[8];
    const float* gamma = (const float*)d_in[9];
    const float* beta  = (const float*)d_in[10];
    float* out = (float*)d_out;

    float* Og;
    __nv_bfloat16 *xhi, *xlo, *whi, *wlo;
    __nv_bfloat16 *qhi, *qlo, *khi, *klo, *vhi, *vlo;
    cudaGetSymbolAddress((void**)&Og, g_O);
    cudaGetSymbolAddress((void**)&xhi, g_Xhi);
    cudaGetSymbolAddress((void**)&xlo, g_Xlo);
    cudaGetSymbolAddress((void**)&whi, g_Wthi);
    cudaGetSymbolAddress((void**)&wlo, g_Wtlo);
    cudaGetSymbolAddress((void**)&qhi, g_Qhi);
    cudaGetSymbolAddress((void**)&qlo, g_Qlo);
    cudaGetSymbolAddress((void**)&khi, g_Khi);
    cudaGetSymbolAddress((void**)&klo, g_Klo);
    cudaGetSymbolAddress((void**)&vhi, g_Vhi);
    cudaGetSymbolAddress((void**)&vlo, g_Vlo);

    cudaFuncSetAttribute(gemm_wmma_kernel, cudaFuncAttributeMaxDynamicSharedMemorySize,
                         GEMM_SMEM_BYTES);
    cudaFuncSetAttribute(attn_reg_kernel, cudaFuncAttributeMaxDynamicSharedMemorySize,
                         ATTN_SMEM);

    dim3 cxgrid(NROWS * Dm / (256 * 4));
    dim3 cwgrid(Dm / 32, Dm / 32);
    dim3 cwblk(32, 8);
    dim3 ggrid(Dm / 128, NROWS / 64);

    const float* Xs[3] = {q, k, v};
    const float* Ws[3] = {Wq, Wk, Wv};
    const float* bs[3] = {bq, bk, bv};
    __nv_bfloat16* Yhs[3] = {qhi, khi, vhi};
    __nv_bfloat16* Yls[3] = {qlo, klo, vlo};
    float scales[3] = {QSCALE, 1.0f, 1.0f};
    for (int i = 0; i < 3; i++) {
        convert_x_kernel<<<cxgrid, 256>>>(Xs[i], xhi, xlo);
        convert_w_kernel<<<cwgrid, cwblk>>>(Ws[i], whi, wlo);
        gemm_wmma_kernel<<<ggrid, 256, GEMM_SMEM_BYTES>>>(xhi, xlo, whi, wlo,
                                                          bs[i], Yhs[i], Yls[i], scales[i]);
    }

    attn_reg_kernel<<<dim3(Sseq / 128, Bsz * Hh), 256, ATTN_SMEM>>>(
        qhi, qlo, khi, klo, vhi, vlo, Og);

    ln_kernel<<<NROWS, 256>>>(Og, gamma, beta, out);
}

// round 6
// speedup vs baseline: 2.6412x; 1.1735x over previous
#include <cuda_runtime.h>
#include <cuda_bf16.h>
#include <math.h>
#include <stdint.h>

#define Bsz   4
#define Sseq  2048
#define Dm    768
#define Hh    16
#define DHh   48
#define NROWS (Bsz * Sseq)

// softmax scale (1/sqrt(48)) * log2(e): folded into Q projection; exp2 in softmax
#define QSCALE 0.2082351f

// Scratch (__device__ globals per allocation-free rule)
__device__ float g_O[NROWS * Dm];
__device__ __nv_bfloat16 g_Xhi[NROWS * Dm];
__device__ __nv_bfloat16 g_Xlo[NROWS * Dm];
__device__ __nv_bfloat16 g_Wthi[Dm * Dm];   // transposed: [n][k]
__device__ __nv_bfloat16 g_Wtlo[Dm * Dm];
__device__ __nv_bfloat16 g_Qhi[NROWS * Dm];
__device__ __nv_bfloat16 g_Qlo[NROWS * Dm];
__device__ __nv_bfloat16 g_Khi[NROWS * Dm];
__device__ __nv_bfloat16 g_Klo[NROWS * Dm];
__device__ __nv_bfloat16 g_Vhi[NROWS * Dm];
__device__ __nv_bfloat16 g_Vlo[NROWS * Dm];

// ============================ PTX helpers ==================================
__device__ __forceinline__ uint32_t smem_u32(const void* p) {
    uint32_t a;
    asm("{ .reg .u64 t; cvta.to.shared.u64 t, %1; cvt.u32.u64 %0, t; }" : "=r"(a) : "l"(p));
    return a;
}
__device__ __forceinline__ float ex2(float x) {
    float y; asm("ex2.approx.ftz.f32 %0, %1;" : "=f"(y) : "f"(x)); return y;
}
#define MMA16816(C, a0, a1, a2, a3, b0, b1)                                   \
    asm volatile("mma.sync.aligned.m16n8k16.row.col.f32.bf16.bf16.f32 "       \
        "{%0,%1,%2,%3}, {%4,%5,%6,%7}, {%8,%9}, {%0,%1,%2,%3};"               \
        : "+f"((C)[0]), "+f"((C)[1]), "+f"((C)[2]), "+f"((C)[3])              \
        : "r"(a0), "r"(a1), "r"(a2), "r"(a3), "r"(b0), "r"(b1))
#define LDSM_X4(r0, r1, r2, r3, addr)                                         \
    asm volatile("ldmatrix.sync.aligned.m8n8.x4.shared.b16 {%0,%1,%2,%3}, [%4];" \
        : "=r"(r0), "=r"(r1), "=r"(r2), "=r"(r3) : "r"(addr))
#define LDSM_X2(r0, r1, addr)                                                 \
    asm volatile("ldmatrix.sync.aligned.m8n8.x2.shared.b16 {%0,%1}, [%2];"    \
        : "=r"(r0), "=r"(r1) : "r"(addr))
#define LDSM_X2T(r0, r1, addr)                                                \
    asm volatile("ldmatrix.sync.aligned.m8n8.x2.trans.shared.b16 {%0,%1}, [%2];" \
        : "=r"(r0), "=r"(r1) : "r"(addr))
#define CP_ASYNC16(sa, ga)                                                    \
    asm volatile("cp.async.cg.shared.global [%0], [%1], 16;" :: "r"(sa), "l"(ga))
#define CP_COMMIT() asm volatile("cp.async.commit_group;" ::: "memory")
#define CP_WAIT1()  asm volatile("cp.async.wait_group 1;" ::: "memory")
#define CP_WAIT0()  asm volatile("cp.async.wait_group 0;" ::: "memory")

__device__ __forceinline__ uint32_t pack_split(float x, float y, uint32_t& lo) {
    __nv_bfloat16 hx = __float2bfloat16_rn(x);
    __nv_bfloat16 hy = __float2bfloat16_rn(y);
    __nv_bfloat16 lx = __float2bfloat16_rn(x - __bfloat162float(hx));
    __nv_bfloat16 ly = __float2bfloat16_rn(y - __bfloat162float(hy));
    __nv_bfloat162 h2(hx, hy), l2(lx, ly);
    lo = *(uint32_t*)&l2;
    return *(uint32_t*)&h2;
}

// ============================ converters ===================================
__global__ __launch_bounds__(256) void convert_x_kernel(
    const float* __restrict__ X, __nv_bfloat16* __restrict__ hi,
    __nv_bfloat16* __restrict__ lo)
{
    int idx = (blockIdx.x * 256 + threadIdx.x) * 4;
    float4 v = *(const float4*)(X + idx);
    __nv_bfloat16 h0 = __float2bfloat16_rn(v.x);
    __nv_bfloat16 h1 = __float2bfloat16_rn(v.y);
    __nv_bfloat16 h2 = __float2bfloat16_rn(v.z);
    __nv_bfloat16 h3 = __float2bfloat16_rn(v.w);
    __nv_bfloat16 l0 = __float2bfloat16_rn(v.x - __bfloat162float(h0));
    __nv_bfloat16 l1 = __float2bfloat16_rn(v.y - __bfloat162float(h1));
    __nv_bfloat16 l2 = __float2bfloat16_rn(v.z - __bfloat162float(h2));
    __nv_bfloat16 l3 = __float2bfloat16_rn(v.w - __bfloat162float(h3));
    __nv_bfloat162 hp0 = __nv_bfloat162(h0, h1), hp1 = __nv_bfloat162(h2, h3);
    __nv_bfloat162 lp0 = __nv_bfloat162(l0, l1), lp1 = __nv_bfloat162(l2, l3);
    uint2 hu, lu;
    hu.x = *(uint32_t*)&hp0; hu.y = *(uint32_t*)&hp1;
    lu.x = *(uint32_t*)&lp0; lu.y = *(uint32_t*)&lp1;
    *(uint2*)(hi + idx) = hu;
    *(uint2*)(lo + idx) = lu;
}

__global__ __launch_bounds__(256) void convert_w_kernel(
    const float* __restrict__ W, __nv_bfloat16* __restrict__ hi,
    __nv_bfloat16* __restrict__ lo)
{
    __shared__ float tile[32][33];
    int tx = threadIdx.x, ty = threadIdx.y;
    int bx = blockIdx.x, by = blockIdx.y;
#pragma unroll
    for (int i = 0; i < 4; i++) {
        int k = by * 32 + ty + i * 8;
        int n = bx * 32 + tx;
        tile[ty + i * 8][tx] = W[k * Dm + n];
    }
    __syncthreads();
#pragma unroll
    for (int i = 0; i < 4; i++) {
        int n = bx * 32 + ty + i * 8;
        int k = by * 32 + tx;
        float v = tile[tx][ty + i * 8];
        __nv_bfloat16 h = __float2bfloat16_rn(v);
        __nv_bfloat16 l = __float2bfloat16_rn(v - __bfloat162float(h));
        hi[n * Dm + k] = h;
        lo[n * Dm + k] = l;
    }
}

// ======================= mma.sync GEMM (split-3 bf16) ======================
// Y[8192,768] = (X @ W + bias) * scale -> split bf16 out.
// CTA tile 128x128, BK=32, cp.async double buffer, 8 warps, warp tile 64x32.
#define GLDA  40                              // padded row: 40 bf16 = 80 B
#define GPART (128 * GLDA * 2)                // 10240 B per operand array
#define GBUF  (4 * GPART)                     // Ahi,Alo,Bhi,Blo = 40960 B
#define GEMM_SMEM_BYTES (2 * GBUF)            // 81920 B
#define GNCHK (Dm / 32)                       // 24

__global__ __launch_bounds__(256, 1) void gemm_mma_kernel(
    const __nv_bfloat16* __restrict__ Ahi, const __nv_bfloat16* __restrict__ Alo,
    const __nv_bfloat16* __restrict__ Bhi, const __nv_bfloat16* __restrict__ Blo,
    const float* __restrict__ bias, __nv_bfloat16* __restrict__ Yhi,
    __nv_bfloat16* __restrict__ Ylo, float scale)
{
    extern __shared__ __align__(128) char smraw[];
    uint32_t smb = smem_u32(smraw);
    int tid = threadIdx.x;
    int w = tid >> 5, lane = tid & 31;
    int bm = blockIdx.y * 128;
    int bn = blockIdx.x * 128;

    int wm = (w >> 2) * 64;          // warp m origin (0 or 64)
    int wn = (w & 3) * 32;           // warp n origin (0,32,64,96)

    // ldmatrix lane mappings (validated in attention kernel)
    int mat = lane >> 3;
    int arow = ((mat & 1) << 3) + (lane & 7);   // A: mat0 rows0-7 k0-7, mat1 rows8-15 k0-7, ...
    int acol8 = (mat >> 1) << 3;
    int brow = ((mat >> 1) << 3) + (lane & 7);  // B: mat0 n0-7 k0-7, mat1 n0-7 k8-15, ...
    int bcol8 = (mat & 1) << 3;

    float c[4][4][4];
#pragma unroll
    for (int mf = 0; mf < 4; mf++)
#pragma unroll
        for (int nf = 0; nf < 4; nf++)
#pragma unroll
            for (int e = 0; e < 4; e++) c[mf][nf][e] = 0.f;

    // cp.async issue: 2048 16B transfers per chunk, 8 per thread
    // idx: part = idx>>9 (0:Ahi 1:Alo 2:Bhi 3:Blo), row = (idx&511)>>2, seg = idx&3
    const __nv_bfloat16* srcs[4] = {Ahi, Alo, Bhi, Blo};

#define GEMM_ISSUE(c0, bufsel) do {                                           \
    int k0_ = (c0) * 32;                                                      \
    uint32_t bb_ = smb + (bufsel) * GBUF;                                     \
    _Pragma("unroll")                                                         \
    for (int it = 0; it < 8; it++) {                                          \
        int idx = tid + it * 256;                                             \
        int part = idx >> 9;                                                  \
        int rem = idx & 511;                                                  \
        int row = rem >> 2, seg = rem & 3;                                    \
        int grow = (part < 2 ? bm : bn) + row;                                \
        const __nv_bfloat16* ga = srcs[part] + (size_t)grow * Dm + k0_ + seg * 8; \
        uint32_t sa = bb_ + part * GPART + row * (GLDA * 2) + seg * 16;       \
        CP_ASYNC16(sa, ga);                                                   \
    }                                                                         \
    CP_COMMIT();                                                              \
} while (0)

    GEMM_ISSUE(0, 0);

    for (int cc = 0; cc < GNCHK; cc++) {
        int buf = cc & 1;
        if (cc + 1 < GNCHK) {
            GEMM_ISSUE(cc + 1, buf ^ 1);
            CP_WAIT1();
        } else {
            CP_WAIT0();
        }
        __syncthreads();

        uint32_t bb = smb + buf * GBUF;
        uint32_t sAh = bb, sAl = bb + GPART, sBh = bb + 2 * GPART, sBl = bb + 3 * GPART;

#pragma unroll
        for (int ks = 0; ks < 2; ks++) {
            uint32_t ah[4][4], al[4][4];
#pragma unroll
            for (int mf = 0; mf < 4; mf++) {
                uint32_t a = ((wm + mf * 16 + arow) * GLDA + ks * 16 + acol8) * 2;
                LDSM_X4(ah[mf][0], ah[mf][1], ah[mf][2], ah[mf][3], sAh + a);
                LDSM_X4(al[mf][0], al[mf][1], al[mf][2], al[mf][3], sAl + a);
            }
            uint32_t bh[4][2], bl[4][2];
#pragma unroll
            for (int nf2 = 0; nf2 < 2; nf2++) {
                uint32_t a = ((wn + nf2 * 16 + brow) * GLDA + ks * 16 + bcol8) * 2;
                uint32_t r0, r1, r2, r3;
                LDSM_X4(r0, r1, r2, r3, sBh + a);
                bh[nf2 * 2][0] = r0; bh[nf2 * 2][1] = r1;
                bh[nf2 * 2 + 1][0] = r2; bh[nf2 * 2 + 1][1] = r3;
                LDSM_X4(r0, r1, r2, r3, sBl + a);
                bl[nf2 * 2][0] = r0; bl[nf2 * 2][1] = r1;
                bl[nf2 * 2 + 1][0] = r2; bl[nf2 * 2 + 1][1] = r3;
            }
#pragma unroll
            for (int mf = 0; mf < 4; mf++)
#pragma unroll
                for (int nf = 0; nf < 4; nf++) {
                    MMA16816(c[mf][nf], ah[mf][0], ah[mf][1], ah[mf][2], ah[mf][3],
                             bh[nf][0], bh[nf][1]);
                    MMA16816(c[mf][nf], ah[mf][0], ah[mf][1], ah[mf][2], ah[mf][3],
                             bl[nf][0], bl[nf][1]);
                    MMA16816(c[mf][nf], al[mf][0], al[mf][1], al[mf][2], al[mf][3],
                             bh[nf][0], bh[nf][1]);
                }
        }
        __syncthreads();
    }

    // Epilogue: stage f32 into smem (64 KB, aliases buffers), then coalesced out
    float* sOut = (float*)smraw;
    int g = lane >> 2, t4 = lane & 3;
#pragma unroll
    for (int mf = 0; mf < 4; mf++) {
        int m0 = wm + mf * 16 + g;
#pragma unroll
        for (int nf = 0; nf < 4; nf++) {
            int col = wn + nf * 8 + t4 * 2;
            sOut[m0 * 128 + col]       = c[mf][nf][0];
            sOut[m0 * 128 + col + 1]   = c[mf][nf][1];
            sOut[(m0 + 8) * 128 + col]     = c[mf][nf][2];
            sOut[(m0 + 8) * 128 + col + 1] = c[mf][nf][3];
        }
    }
    __syncthreads();

#pragma unroll
    for (int it = 0; it < 16; it++) {
        int idx = tid + it * 256;          // 4096 float4 slots (128 x 32)
        int row = idx >> 5, c4 = (idx & 31) * 4;
        float4 o = *(float4*)(sOut + row * 128 + c4);
        const float* bp = bias + bn + c4;
        float y0 = (o.x + bp[0]) * scale;
        float y1 = (o.y + bp[1]) * scale;
        float y2 = (o.z + bp[2]) * scale;
        float y3 = (o.w + bp[3]) * scale;
        uint32_t l01, l23;
        uint32_t h01 = pack_split(y0, y1, l01);
        uint32_t h23 = pack_split(y2, y3, l23);
        uint2 hu = make_uint2(h01, h23);
        uint2 lu = make_uint2(l01, l23);
        size_t off = (size_t)(bm + row) * Dm + bn + c4;
        *(uint2*)(Yhi + off) = hu;
        *(uint2*)(Ylo + off) = lu;
    }
}

// ============== register-resident flash attention (mma.sync) ===============
#define LDA 56
#define QARR (128 * LDA * 2)
#define KARR (64 * LDA * 2)
#define BUFB (4 * KARR)
#define ATTN_SMEM (2 * QARR + 3 * BUFB)

__global__ __launch_bounds__(256) void attn_reg_kernel(
    const __nv_bfloat16* __restrict__ Qh_g, const __nv_bfloat16* __restrict__ Ql_g,
    const __nv_bfloat16* __restrict__ Kh_g, const __nv_bfloat16* __restrict__ Kl_g,
    const __nv_bfloat16* __restrict__ Vh_g, const __nv_bfloat16* __restrict__ Vl_g,
    float* __restrict__ Og)
{
    extern __shared__ __align__(128) char smraw[];
    uint32_t smb = smem_u32(smraw);
    __nv_bfloat16* Qh = (__nv_bfloat16*)smraw;
    __nv_bfloat16* Ql = (__nv_bfloat16*)(smraw + QARR);

    int qt = (int)gridDim.x - 1 - (int)blockIdx.x;
    int bh = blockIdx.y;
    int b = bh >> 4, h = bh & 15;
    int tid = threadIdx.x;
    int w = tid >> 5, lane = tid & 31;
    int rowbase = b * Sseq;
    int q0 = qt * 128;
    int hoff = h * DHh;
    int ntiles = 2 * qt + 2;

    {
#pragma unroll
        for (int it = 0; it < 6; it++) {
            int s = tid + it * 256;
            int arr = s / 384, rem = s - arr * 384;
            int r = rem / 6, c16 = rem - r * 6;
            const __nv_bfloat16* src = (arr == 0) ? Kh_g : (arr == 1) ? Kl_g :
                                       (arr == 2) ? Vh_g : Vl_g;
            const __nv_bfloat16* ga = src + (size_t)(rowbase + r) * Dm + hoff + c16 * 8;
            uint32_t sa = smb + 2 * QARR + arr * KARR + r * (LDA * 2) + c16 * 16;
            CP_ASYNC16(sa, ga);
        }
        CP_COMMIT();
    }

    for (int s = tid; s < 1536; s += 256) {
        int arr = s / 768;
        int rem = s - arr * 768;
        int r = rem / 6, c8 = (rem - r * 6) * 8;
        const __nv_bfloat16* src = (arr ? Ql_g : Qh_g) +
            (size_t)(rowbase + q0 + r) * Dm + hoff + c8;
        __nv_bfloat16* dst = (arr ? Ql : Qh) + r * LDA + c8;
        *(uint4*)dst = *(const uint4*)src;
    }
    __syncthreads();

    int mat = lane >> 3;
    int qrow_loc = ((mat & 1) << 3) + (lane & 7);
    int qcol8 = (mat >> 1) << 3;
    uint32_t qh[3][4], ql[3][4];
#pragma unroll
    for (int ks = 0; ks < 3; ks++) {
        uint32_t a = smb + ((w * 16 + qrow_loc) * LDA + ks * 16 + qcol8) * 2;
        LDSM_X4(qh[ks][0], qh[ks][1], qh[ks][2], qh[ks][3], a);
        LDSM_X4(ql[ks][0], ql[ks][1], ql[ks][2], ql[ks][3], a + QARR);
    }

    int g = lane >> 2, t4 = lane & 3;
    int lane16 = lane & 15;
    int krow_loc = lane16 & 7;
    int khalf = (lane16 >> 3) << 3;

    float m0 = -1e30f, m1 = -1e30f, l0 = 0.f, l1 = 0.f;
    float o[6][4];
#pragma unroll
    for (int on = 0; on < 6; on++)
#pragma unroll
        for (int e = 0; e < 4; e++) o[on][e] = 0.f;

    for (int j = 0; j < ntiles; j++) {
        if (j + 1 < ntiles) {
            int k0n = (j + 1) * 64;
            uint32_t bb = smb + 2 * QARR + ((j + 1) % 3) * BUFB;
#pragma unroll
            for (int it = 0; it < 6; it++) {
                int s = tid + it * 256;
                int arr = s / 384, rem = s - arr * 384;
                int r = rem / 6, c16 = rem - r * 6;
                const __nv_bfloat16* src = (arr == 0) ? Kh_g : (arr == 1) ? Kl_g :
                                           (arr == 2) ? Vh_g : Vl_g;
                const __nv_bfloat16* ga = src + (size_t)(rowbase + k0n + r) * Dm + hoff + c16 * 8;
                uint32_t sa = bb + arr * KARR + r * (LDA * 2) + c16 * 16;
                CP_ASYNC16(sa, ga);
            }
            CP_COMMIT();
            CP_WAIT1();
        } else {
            CP_WAIT0();
        }
        __syncthreads();

        uint32_t bufb = smb + 2 * QARR + (j % 3) * BUFB;
        uint32_t bufKh = bufb, bufKl = bufb + KARR;
        uint32_t bufVh = bufb + 2 * KARR, bufVl = bufb + 3 * KARR;

        float sc[8][4];
#pragma unroll
        for (int jn = 0; jn < 8; jn++) {
#pragma unroll
            for (int e = 0; e < 4; e++) sc[jn][e] = 0.f;
            uint32_t kbase = ((jn * 8 + krow_loc) * LDA + khalf) * 2;
#pragma unroll
            for (int ks = 0; ks < 3; ks++) {
                uint32_t kh0, kh1, kl0, kl1;
                LDSM_X2(kh0, kh1, bufKh + kbase + ks * 32);
                LDSM_X2(kl0, kl1, bufKl + kbase + ks * 32);
                MMA16816(sc[jn], qh[ks][0], qh[ks][1], qh[ks][2], qh[ks][3], kh0, kh1);
                MMA16816(sc[jn], qh[ks][0], qh[ks][1], qh[ks][2], qh[ks][3], kl0, kl1);
                MMA16816(sc[jn], ql[ks][0], ql[ks][1], ql[ks][2], ql[ks][3], kh0, kh1);
            }
        }

        int k0 = j * 64;
        if (j >= 2 * qt) {
            int qg0 = q0 + w * 16 + g;
#pragma unroll
            for (int jn = 0; jn < 8; jn++) {
                int cix = k0 + jn * 8 + 2 * t4;
                if (qg0 < cix)     sc[jn][0] = -1e30f;
                if (qg0 < cix + 1) sc[jn][1] = -1e30f;
                if (qg0 + 8 < cix)     sc[jn][2] = -1e30f;
                if (qg0 + 8 < cix + 1) sc[jn][3] = -1e30f;
            }
        }

        float mx0 = -1e30f, mx1 = -1e30f;
#pragma unroll
        for (int jn = 0; jn < 8; jn++) {
            mx0 = fmaxf(mx0, fmaxf(sc[jn][0], sc[jn][1]));
            mx1 = fmaxf(mx1, fmaxf(sc[jn][2], sc[jn][3]));
        }
        mx0 = fmaxf(mx0, __shfl_xor_sync(0xffffffffu, mx0, 1));
        mx0 = fmaxf(mx0, __shfl_xor_sync(0xffffffffu, mx0, 2));
        mx1 = fmaxf(mx1, __shfl_xor_sync(0xffffffffu, mx1, 1));
        mx1 = fmaxf(mx1, __shfl_xor_sync(0xffffffffu, mx1, 2));
        float mn0 = fmaxf(m0, mx0), mn1 = fmaxf(m1, mx1);
        float al0 = ex2(m0 - mn0), al1 = ex2(m1 - mn1);
        m0 = mn0; m1 = mn1;
        float ps0 = 0.f, ps1 = 0.f;
#pragma unroll
        for (int jn = 0; jn < 8; jn++) {
            sc[jn][0] = ex2(sc[jn][0] - mn0);
            sc[jn][1] = ex2(sc[jn][1] - mn0);
            sc[jn][2] = ex2(sc[jn][2] - mn1);
            sc[jn][3] = ex2(sc[jn][3] - mn1);
            ps0 += sc[jn][0] + sc[jn][1];
            ps1 += sc[jn][2] + sc[jn][3];
        }
        ps0 += __shfl_xor_sync(0xffffffffu, ps0, 1);
        ps0 += __shfl_xor_sync(0xffffffffu, ps0, 2);
        ps1 += __shfl_xor_sync(0xffffffffu, ps1, 1);
        ps1 += __shfl_xor_sync(0xffffffffu, ps1, 2);
        l0 = l0 * al0 + ps0;
        l1 = l1 * al1 + ps1;

#pragma unroll
        for (int on = 0; on < 6; on++) {
            o[on][0] *= al0; o[on][1] *= al0;
            o[on][2] *= al1; o[on][3] *= al1;
        }
#pragma unroll
        for (int ks = 0; ks < 4; ks++) {
            uint32_t pa[4], pl[4];
            pa[0] = pack_split(sc[2*ks][0],   sc[2*ks][1],   pl[0]);
            pa[1] = pack_split(sc[2*ks][2],   sc[2*ks][3],   pl[1]);
            pa[2] = pack_split(sc[2*ks+1][0], sc[2*ks+1][1], pl[2]);
            pa[3] = pack_split(sc[2*ks+1][2], sc[2*ks+1][3], pl[3]);
            uint32_t vrow = ((ks * 16 + krow_loc + khalf) * LDA) * 2;
#pragma unroll
            for (int on = 0; on < 6; on++) {
                uint32_t vh0, vh1, vl0, vl1;
                LDSM_X2T(vh0, vh1, bufVh + vrow + on * 16);
                LDSM_X2T(vl0, vl1, bufVl + vrow + on * 16);
                MMA16816(o[on], pa[0], pa[1], pa[2], pa[3], vh0, vh1);
                MMA16816(o[on], pa[0], pa[1], pa[2], pa[3], vl0, vl1);
                MMA16816(o[on], pl[0], pl[1], pl[2], pl[3], vh0, vh1);
            }
        }
        __syncthreads();
    }

    float inv0 = 1.f / l0, inv1 = 1.f / l1;
    float* op0 = Og + (size_t)(rowbase + q0 + w * 16 + g) * Dm + hoff + 2 * t4;
    float* op1 = op0 + 8 * Dm;
#pragma unroll
    for (int on = 0; on < 6; on++) {
        float2 r0 = make_float2(o[on][0] * inv0, o[on][1] * inv0);
        float2 r1 = make_float2(o[on][2] * inv1, o[on][3] * inv1);
        *(float2*)(op0 + on * 8) = r0;
        *(float2*)(op1 + on * 8) = r1;
    }
}

// ---------------------------------------------------------------------------
// LayerNorm (unchanged)
// ---------------------------------------------------------------------------
__global__ __launch_bounds__(256) void ln_kernel(
    const float* __restrict__ X, const float* __restrict__ gamma,
    const float* __restrict__ beta, float* __restrict__ Y)
{
    int row = blockIdx.x;
    int tid = threadIdx.x;
    const float* x = X + (size_t)row * Dm;

    float v0 = x[tid], v1 = x[tid + 256], v2 = x[tid + 512];
    float s  = v0 + v1 + v2;
    float sq = v0 * v0 + v1 * v1 + v2 * v2;

#pragma unroll
    for (int off = 16; off > 0; off >>= 1) {
        s  += __shfl_xor_sync(0xffffffffu, s, off);
        sq += __shfl_xor_sync(0xffffffffu, sq, off);
    }
    __shared__ float red_s[8], red_q[8];
    int wid = tid >> 5, lid = tid & 31;
    if (lid == 0) { red_s[wid] = s; red_q[wid] = sq; }
    __syncthreads();
    if (wid == 0) {
        float a = (lid < 8) ? red_s[lid] : 0.f;
        float bq2 = (lid < 8) ? red_q[lid] : 0.f;
#pragma unroll
        for (int off = 4; off > 0; off >>= 1) {
            a += __shfl_xor_sync(0xffffffffu, a, off);
            bq2 += __shfl_xor_sync(0xffffffffu, bq2, off);
        }
        if (lid == 0) { red_s[0] = a; red_q[0] = bq2; }
    }
    __syncthreads();
    float mu  = red_s[0] * (1.f / Dm);
    float var = red_q[0] * (1.f / Dm) - mu * mu;
    float inv = rsqrtf(var + 1e-3f);

    float* y = Y + (size_t)row * Dm;
    y[tid]       = (v0 - mu) * inv * gamma[tid]       + beta[tid];
    y[tid + 256] = (v1 - mu) * inv * gamma[tid + 256] + beta[tid + 256];
    y[tid + 512] = (v2 - mu) * inv * gamma[tid + 512] + beta[tid + 512];
}

// ---------------------------------------------------------------------------
extern "C" void kernel_launch(void* const* d_in, const int* in_sizes, int n_in,
                              void* d_out, int out_size)
{
    const float* q     = (const float*)d_in[0];
    const float* k     = (const float*)d_in[1];
    const float* v     = (const float*)d_in[2];
    const float* Wq    = (const float*)d_in[3];
    const float* bq    = (const float*)d_in[4];
    const float* Wk    = (const float*)d_in[5];
    const float* bk    = (const float*)d_in[6];
    const float* Wv    = (const float*)d_in[7];
    const float* bv    = (const float*)d_in[8];
    const float* gamma = (const float*)d_in[9];
    const float* beta  = (const float*)d_in[10];
    float* out = (float*)d_out;

    float* Og;
    __nv_bfloat16 *xhi, *xlo, *whi, *wlo;
    __nv_bfloat16 *qhi, *qlo, *khi, *klo, *vhi, *vlo;
    cudaGetSymbolAddress((void**)&Og, g_O);
    cudaGetSymbolAddress((void**)&xhi, g_Xhi);
    cudaGetSymbolAddress((void**)&xlo, g_Xlo);
    cudaGetSymbolAddress((void**)&whi, g_Wthi);
    cudaGetSymbolAddress((void**)&wlo, g_Wtlo);
    cudaGetSymbolAddress((void**)&qhi, g_Qhi);
    cudaGetSymbolAddress((void**)&qlo, g_Qlo);
    cudaGetSymbolAddress((void**)&khi, g_Khi);
    cudaGetSymbolAddress((void**)&klo, g_Klo);
    cudaGetSymbolAddress((void**)&vhi, g_Vhi);
    cudaGetSymbolAddress((void**)&vlo, g_Vlo);

    cudaFuncSetAttribute(gemm_mma_kernel, cudaFuncAttributeMaxDynamicSharedMemorySize,
                         GEMM_SMEM_BYTES);
    cudaFuncSetAttribute(attn_reg_kernel, cudaFuncAttributeMaxDynamicSharedMemorySize,
                         ATTN_SMEM);

    dim3 cxgrid(NROWS * Dm / (256 * 4));
    dim3 cwgrid(Dm / 32, Dm / 32);
    dim3 cwblk(32, 8);
    dim3 ggrid(Dm / 128, NROWS / 128);   // (6, 64)

    const float* Xs[3] = {q, k, v};
    const float* Ws[3] = {Wq, Wk, Wv};
    const float* bs[3] = {bq, bk, bv};
    __nv_bfloat16* Yhs[3] = {qhi, khi, vhi};
    __nv_bfloat16* Yls[3] = {qlo, klo, vlo};
    float scales[3] = {QSCALE, 1.0f, 1.0f};
    for (int i = 0; i < 3; i++) {
        convert_x_kernel<<<cxgrid, 256>>>(Xs[i], xhi, xlo);
        convert_w_kernel<<<cwgrid, cwblk>>>(Ws[i], whi, wlo);
        gemm_mma_kernel<<<ggrid, 256, GEMM_SMEM_BYTES>>>(xhi, xlo, whi, wlo,
                                                         bs[i], Yhs[i], Yls[i], scales[i]);
    }

    attn_reg_kernel<<<dim3(Sseq / 128, Bsz * Hh), 256, ATTN_SMEM>>>(
        qhi, qlo, khi, klo, vhi, vlo, Og);

    ln_kernel<<<NROWS, 256>>>(Og, gamma, beta, out);
}

// round 7
// speedup vs baseline: 2.9701x; 1.1245x over previous
#include <cuda_runtime.h>
#include <cuda_bf16.h>
#include <math.h>
#include <stdint.h>

#define Bsz   4
#define Sseq  2048
#define Dm    768
#define Hh    16
#define DHh   48
#define NROWS (Bsz * Sseq)
#define XELEMS ((size_t)NROWS * Dm)
#define WELEMS ((size_t)Dm * Dm)

// softmax scale (1/sqrt(48)) * log2(e): folded into Q projection; exp2 in softmax
#define QSCALE 0.2082351f

// Scratch (__device__ globals per allocation-free rule)
__device__ float g_O[NROWS * Dm];
__device__ __nv_bfloat16 g_Xhi[3 * XELEMS];   // split X for q,k,v
__device__ __nv_bfloat16 g_Xlo[3 * XELEMS];
__device__ __nv_bfloat16 g_Wthi[3 * WELEMS];  // transposed W [n][k] for q,k,v
__device__ __nv_bfloat16 g_Wtlo[3 * WELEMS];
__device__ __nv_bfloat16 g_Qhi[XELEMS];
__device__ __nv_bfloat16 g_Qlo[XELEMS];
__device__ __nv_bfloat16 g_Khi[XELEMS];
__device__ __nv_bfloat16 g_Klo[XELEMS];
__device__ __nv_bfloat16 g_Vhi[XELEMS];
__device__ __nv_bfloat16 g_Vlo[XELEMS];

// ============================ PTX helpers ==================================
__device__ __forceinline__ uint32_t smem_u32(const void* p) {
    uint32_t a;
    asm("{ .reg .u64 t; cvta.to.shared.u64 t, %1; cvt.u32.u64 %0, t; }" : "=r"(a) : "l"(p));
    return a;
}
__device__ __forceinline__ float ex2(float x) {
    float y; asm("ex2.approx.ftz.f32 %0, %1;" : "=f"(y) : "f"(x)); return y;
}
#define MMA16816(C, a0, a1, a2, a3, b0, b1)                                   \
    asm volatile("mma.sync.aligned.m16n8k16.row.col.f32.bf16.bf16.f32 "       \
        "{%0,%1,%2,%3}, {%4,%5,%6,%7}, {%8,%9}, {%0,%1,%2,%3};"               \
        : "+f"((C)[0]), "+f"((C)[1]), "+f"((C)[2]), "+f"((C)[3])              \
        : "r"(a0), "r"(a1), "r"(a2), "r"(a3), "r"(b0), "r"(b1))
#define LDSM_X4(r0, r1, r2, r3, addr)                                         \
    asm volatile("ldmatrix.sync.aligned.m8n8.x4.shared.b16 {%0,%1,%2,%3}, [%4];" \
        : "=r"(r0), "=r"(r1), "=r"(r2), "=r"(r3) : "r"(addr))
#define LDSM_X2(r0, r1, addr)                                                 \
    asm volatile("ldmatrix.sync.aligned.m8n8.x2.shared.b16 {%0,%1}, [%2];"    \
        : "=r"(r0), "=r"(r1) : "r"(addr))
#define LDSM_X2T(r0, r1, addr)                                                \
    asm volatile("ldmatrix.sync.aligned.m8n8.x2.trans.shared.b16 {%0,%1}, [%2];" \
        : "=r"(r0), "=r"(r1) : "r"(addr))
#define CP_ASYNC16(sa, ga)                                                    \
    asm volatile("cp.async.cg.shared.global [%0], [%1], 16;" :: "r"(sa), "l"(ga))
#define CP_COMMIT() asm volatile("cp.async.commit_group;" ::: "memory")
#define CP_WAIT1()  asm volatile("cp.async.wait_group 1;" ::: "memory")
#define CP_WAIT0()  asm volatile("cp.async.wait_group 0;" ::: "memory")

__device__ __forceinline__ uint32_t pack_split(float x, float y, uint32_t& lo) {
    __nv_bfloat16 hx = __float2bfloat16_rn(x);
    __nv_bfloat16 hy = __float2bfloat16_rn(y);
    __nv_bfloat16 lx = __float2bfloat16_rn(x - __bfloat162float(hx));
    __nv_bfloat16 ly = __float2bfloat16_rn(y - __bfloat162float(hy));
    __nv_bfloat162 h2(hx, hy), l2(lx, ly);
    lo = *(uint32_t*)&l2;
    return *(uint32_t*)&h2;
}

// ============================ converters (batched z=3) ======================
__global__ __launch_bounds__(256) void convert_x_kernel(
    const float* __restrict__ q, const float* __restrict__ k,
    const float* __restrict__ v,
    __nv_bfloat16* __restrict__ hi, __nv_bfloat16* __restrict__ lo)
{
    int z = blockIdx.y;
    const float* X = (z == 0) ? q : (z == 1) ? k : v;
    size_t base = (size_t)z * XELEMS;
    size_t idx = ((size_t)blockIdx.x * 256 + threadIdx.x) * 4;
    float4 val = *(const float4*)(X + idx);
    __nv_bfloat16 h0 = __float2bfloat16_rn(val.x);
    __nv_bfloat16 h1 = __float2bfloat16_rn(val.y);
    __nv_bfloat16 h2 = __float2bfloat16_rn(val.z);
    __nv_bfloat16 h3 = __float2bfloat16_rn(val.w);
    __nv_bfloat16 l0 = __float2bfloat16_rn(val.x - __bfloat162float(h0));
    __nv_bfloat16 l1 = __float2bfloat16_rn(val.y - __bfloat162float(h1));
    __nv_bfloat16 l2 = __float2bfloat16_rn(val.z - __bfloat162float(h2));
    __nv_bfloat16 l3 = __float2bfloat16_rn(val.w - __bfloat162float(h3));
    __nv_bfloat162 hp0 = __nv_bfloat162(h0, h1), hp1 = __nv_bfloat162(h2, h3);
    __nv_bfloat162 lp0 = __nv_bfloat162(l0, l1), lp1 = __nv_bfloat162(l2, l3);
    uint2 hu, lu;
    hu.x = *(uint32_t*)&hp0; hu.y = *(uint32_t*)&hp1;
    lu.x = *(uint32_t*)&lp0; lu.y = *(uint32_t*)&lp1;
    *(uint2*)(hi + base + idx) = hu;
    *(uint2*)(lo + base + idx) = lu;
}

__global__ __launch_bounds__(256) void convert_w_kernel(
    const float* __restrict__ wq, const float* __restrict__ wk,
    const float* __restrict__ wv,
    __nv_bfloat16* __restrict__ hi, __nv_bfloat16* __restrict__ lo)
{
    __shared__ float tile[32][33];
    int z = blockIdx.z;
    const float* W = (z == 0) ? wq : (z == 1) ? wk : wv;
    size_t base = (size_t)z * WELEMS;
    int tx = threadIdx.x, ty = threadIdx.y;
    int bx = blockIdx.x, by = blockIdx.y;
#pragma unroll
    for (int i = 0; i < 4; i++) {
        int kk = by * 32 + ty + i * 8;
        int n = bx * 32 + tx;
        tile[ty + i * 8][tx] = W[kk * Dm + n];
    }
    __syncthreads();
#pragma unroll
    for (int i = 0; i < 4; i++) {
        int n = bx * 32 + ty + i * 8;
        int kk = by * 32 + tx;
        float v = tile[tx][ty + i * 8];
        __nv_bfloat16 h = __float2bfloat16_rn(v);
        __nv_bfloat16 l = __float2bfloat16_rn(v - __bfloat162float(h));
        hi[base + n * Dm + kk] = h;
        lo[base + n * Dm + kk] = l;
    }
}

// ======================= batched mma.sync GEMM (split-3) ===================
// grid.z in {0,1,2} selects (X,W,bias,Y) set. CTA tile 128x128, BK=32.
#define GLDA  40
#define GPART (128 * GLDA * 2)
#define GBUF  (4 * GPART)
#define GEMM_SMEM_BYTES (2 * GBUF)            // 81920 B
#define GNCHK (Dm / 32)

__global__ __launch_bounds__(256, 1) void gemm_mma_kernel(
    const __nv_bfloat16* __restrict__ xhi, const __nv_bfloat16* __restrict__ xlo,
    const __nv_bfloat16* __restrict__ whi, const __nv_bfloat16* __restrict__ wlo,
    const float* __restrict__ bq, const float* __restrict__ bk,
    const float* __restrict__ bv,
    __nv_bfloat16* __restrict__ qhi, __nv_bfloat16* __restrict__ qlo,
    __nv_bfloat16* __restrict__ khi, __nv_bfloat16* __restrict__ klo,
    __nv_bfloat16* __restrict__ vhi, __nv_bfloat16* __restrict__ vlo)
{
    extern __shared__ __align__(128) char smraw[];
    uint32_t smb = smem_u32(smraw);
    int z = blockIdx.z;
    const __nv_bfloat16* Ahi = xhi + (size_t)z * XELEMS;
    const __nv_bfloat16* Alo = xlo + (size_t)z * XELEMS;
    const __nv_bfloat16* Bhi = whi + (size_t)z * WELEMS;
    const __nv_bfloat16* Blo = wlo + (size_t)z * WELEMS;
    const float* bias = (z == 0) ? bq : (z == 1) ? bk : bv;
    __nv_bfloat16* Yhi = (z == 0) ? qhi : (z == 1) ? khi : vhi;
    __nv_bfloat16* Ylo = (z == 0) ? qlo : (z == 1) ? klo : vlo;
    float scale = (z == 0) ? QSCALE : 1.0f;

    int tid = threadIdx.x;
    int w = tid >> 5, lane = tid & 31;
    int bm = blockIdx.y * 128;
    int bn = blockIdx.x * 128;

    int wm = (w >> 2) * 64;
    int wn = (w & 3) * 32;

    int mat = lane >> 3;
    int arow = ((mat & 1) << 3) + (lane & 7);
    int acol8 = (mat >> 1) << 3;
    int brow = ((mat >> 1) << 3) + (lane & 7);
    int bcol8 = (mat & 1) << 3;

    float c[4][4][4];
#pragma unroll
    for (int mf = 0; mf < 4; mf++)
#pragma unroll
        for (int nf = 0; nf < 4; nf++)
#pragma unroll
            for (int e = 0; e < 4; e++) c[mf][nf][e] = 0.f;

    const __nv_bfloat16* srcs[4] = {Ahi, Alo, Bhi, Blo};

#define GEMM_ISSUE(c0, bufsel) do {                                           \
    int k0_ = (c0) * 32;                                                      \
    uint32_t bb_ = smb + (bufsel) * GBUF;                                     \
    _Pragma("unroll")                                                         \
    for (int it = 0; it < 8; it++) {                                          \
        int idx = tid + it * 256;                                             \
        int part = idx >> 9;                                                  \
        int rem = idx & 511;                                                  \
        int row = rem >> 2, seg = rem & 3;                                    \
        int grow = (part < 2 ? bm : bn) + row;                                \
        const __nv_bfloat16* ga = srcs[part] + (size_t)grow * Dm + k0_ + seg * 8; \
        uint32_t sa = bb_ + part * GPART + row * (GLDA * 2) + seg * 16;       \
        CP_ASYNC16(sa, ga);                                                   \
    }                                                                         \
    CP_COMMIT();                                                              \
} while (0)

    GEMM_ISSUE(0, 0);

    for (int cc = 0; cc < GNCHK; cc++) {
        int buf = cc & 1;
        if (cc + 1 < GNCHK) {
            GEMM_ISSUE(cc + 1, buf ^ 1);
            CP_WAIT1();
        } else {
            CP_WAIT0();
        }
        __syncthreads();

        uint32_t bb = smb + buf * GBUF;
        uint32_t sAh = bb, sAl = bb + GPART, sBh = bb + 2 * GPART, sBl = bb + 3 * GPART;

#pragma unroll
        for (int ks = 0; ks < 2; ks++) {
            uint32_t ah[4][4], al[4][4];
#pragma unroll
            for (int mf = 0; mf < 4; mf++) {
                uint32_t a = ((wm + mf * 16 + arow) * GLDA + ks * 16 + acol8) * 2;
                LDSM_X4(ah[mf][0], ah[mf][1], ah[mf][2], ah[mf][3], sAh + a);
                LDSM_X4(al[mf][0], al[mf][1], al[mf][2], al[mf][3], sAl + a);
            }
            uint32_t bh[4][2], bl[4][2];
#pragma unroll
            for (int nf2 = 0; nf2 < 2; nf2++) {
                uint32_t a = ((wn + nf2 * 16 + brow) * GLDA + ks * 16 + bcol8) * 2;
                uint32_t r0, r1, r2, r3;
                LDSM_X4(r0, r1, r2, r3, sBh + a);
                bh[nf2 * 2][0] = r0; bh[nf2 * 2][1] = r1;
                bh[nf2 * 2 + 1][0] = r2; bh[nf2 * 2 + 1][1] = r3;
                LDSM_X4(r0, r1, r2, r3, sBl + a);
                bl[nf2 * 2][0] = r0; bl[nf2 * 2][1] = r1;
                bl[nf2 * 2 + 1][0] = r2; bl[nf2 * 2 + 1][1] = r3;
            }
#pragma unroll
            for (int mf = 0; mf < 4; mf++)
#pragma unroll
                for (int nf = 0; nf < 4; nf++) {
                    MMA16816(c[mf][nf], ah[mf][0], ah[mf][1], ah[mf][2], ah[mf][3],
                             bh[nf][0], bh[nf][1]);
                    MMA16816(c[mf][nf], ah[mf][0], ah[mf][1], ah[mf][2], ah[mf][3],
                             bl[nf][0], bl[nf][1]);
                    MMA16816(c[mf][nf], al[mf][0], al[mf][1], al[mf][2], al[mf][3],
                             bh[nf][0], bh[nf][1]);
                }
        }
        __syncthreads();
    }

    float* sOut = (float*)smraw;
    int g = lane >> 2, t4 = lane & 3;
#pragma unroll
    for (int mf = 0; mf < 4; mf++) {
        int m0 = wm + mf * 16 + g;
#pragma unroll
        for (int nf = 0; nf < 4; nf++) {
            int col = wn + nf * 8 + t4 * 2;
            sOut[m0 * 128 + col]       = c[mf][nf][0];
            sOut[m0 * 128 + col + 1]   = c[mf][nf][1];
            sOut[(m0 + 8) * 128 + col]     = c[mf][nf][2];
            sOut[(m0 + 8) * 128 + col + 1] = c[mf][nf][3];
        }
    }
    __syncthreads();

#pragma unroll
    for (int it = 0; it < 16; it++) {
        int idx = tid + it * 256;
        int row = idx >> 5, c4 = (idx & 31) * 4;
        float4 o = *(float4*)(sOut + row * 128 + c4);
        const float* bp = bias + bn + c4;
        float y0 = (o.x + bp[0]) * scale;
        float y1 = (o.y + bp[1]) * scale;
        float y2 = (o.z + bp[2]) * scale;
        float y3 = (o.w + bp[3]) * scale;
        uint32_t l01, l23;
        uint32_t h01 = pack_split(y0, y1, l01);
        uint32_t h23 = pack_split(y2, y3, l23);
        uint2 hu = make_uint2(h01, h23);
        uint2 lu = make_uint2(l01, l23);
        size_t off = (size_t)(bm + row) * Dm + bn + c4;
        *(uint2*)(Yhi + off) = hu;
        *(uint2*)(Ylo + off) = lu;
    }
}

// ============== register-resident flash attention (mma.sync) ===============
// 104 KB smem -> 2 CTAs/SM; __launch_bounds__(256,2) for the occupancy.
#define LDA 56
#define QARR (128 * LDA * 2)
#define KARR (64 * LDA * 2)
#define BUFB (4 * KARR)
#define ATTN_SMEM (2 * QARR + 3 * BUFB)

__global__ __launch_bounds__(256, 2) void attn_reg_kernel(
    const __nv_bfloat16* __restrict__ Qh_g, const __nv_bfloat16* __restrict__ Ql_g,
    const __nv_bfloat16* __restrict__ Kh_g, const __nv_bfloat16* __restrict__ Kl_g,
    const __nv_bfloat16* __restrict__ Vh_g, const __nv_bfloat16* __restrict__ Vl_g,
    float* __restrict__ Og)
{
    extern __shared__ __align__(128) char smraw[];
    uint32_t smb = smem_u32(smraw);
    __nv_bfloat16* Qh = (__nv_bfloat16*)smraw;
    __nv_bfloat16* Ql = (__nv_bfloat16*)(smraw + QARR);

    int qt = (int)gridDim.x - 1 - (int)blockIdx.x;
    int bh = blockIdx.y;
    int b = bh >> 4, h = bh & 15;
    int tid = threadIdx.x;
    int w = tid >> 5, lane = tid & 31;
    int rowbase = b * Sseq;
    int q0 = qt * 128;
    int hoff = h * DHh;
    int ntiles = 2 * qt + 2;

    {
#pragma unroll
        for (int it = 0; it < 6; it++) {
            int s = tid + it * 256;
            int arr = s / 384, rem = s - arr * 384;
            int r = rem / 6, c16 = rem - r * 6;
            const __nv_bfloat16* src = (arr == 0) ? Kh_g : (arr == 1) ? Kl_g :
                                       (arr == 2) ? Vh_g : Vl_g;
            const __nv_bfloat16* ga = src + (size_t)(rowbase + r) * Dm + hoff + c16 * 8;
            uint32_t sa = smb + 2 * QARR + arr * KARR + r * (LDA * 2) + c16 * 16;
            CP_ASYNC16(sa, ga);
        }
        CP_COMMIT();
    }

    for (int s = tid; s < 1536; s += 256) {
        int arr = s / 768;
        int rem = s - arr * 768;
        int r = rem / 6, c8 = (rem - r * 6) * 8;
        const __nv_bfloat16* src = (arr ? Ql_g : Qh_g) +
            (size_t)(rowbase + q0 + r) * Dm + hoff + c8;
        __nv_bfloat16* dst = (arr ? Ql : Qh) + r * LDA + c8;
        *(uint4*)dst = *(const uint4*)src;
    }
    __syncthreads();

    int mat = lane >> 3;
    int qrow_loc = ((mat & 1) << 3) + (lane & 7);
    int qcol8 = (mat >> 1) << 3;
    uint32_t qh[3][4], ql[3][4];
#pragma unroll
    for (int ks = 0; ks < 3; ks++) {
        uint32_t a = smb + ((w * 16 + qrow_loc) * LDA + ks * 16 + qcol8) * 2;
        LDSM_X4(qh[ks][0], qh[ks][1], qh[ks][2], qh[ks][3], a);
        LDSM_X4(ql[ks][0], ql[ks][1], ql[ks][2], ql[ks][3], a + QARR);
    }

    int g = lane >> 2, t4 = lane & 3;
    int lane16 = lane & 15;
    int krow_loc = lane16 & 7;
    int khalf = (lane16 >> 3) << 3;

    float m0 = -1e30f, m1 = -1e30f, l0 = 0.f, l1 = 0.f;
    float o[6][4];
#pragma unroll
    for (int on = 0; on < 6; on++)
#pragma unroll
        for (int e = 0; e < 4; e++) o[on][e] = 0.f;

    for (int j = 0; j < ntiles; j++) {
        if (j + 1 < ntiles) {
            int k0n = (j + 1) * 64;
            uint32_t bb = smb + 2 * QARR + ((j + 1) % 3) * BUFB;
#pragma unroll
            for (int it = 0; it < 6; it++) {
                int s = tid + it * 256;
                int arr = s / 384, rem = s - arr * 384;
                int r = rem / 6, c16 = rem - r * 6;
                const __nv_bfloat16* src = (arr == 0) ? Kh_g : (arr == 1) ? Kl_g :
                                           (arr == 2) ? Vh_g : Vl_g;
                const __nv_bfloat16* ga = src + (size_t)(rowbase + k0n + r) * Dm + hoff + c16 * 8;
                uint32_t sa = bb + arr * KARR + r * (LDA * 2) + c16 * 16;
                CP_ASYNC16(sa, ga);
            }
            CP_COMMIT();
            CP_WAIT1();
        } else {
            CP_WAIT0();
        }
        __syncthreads();

        uint32_t bufb = smb + 2 * QARR + (j % 3) * BUFB;
        uint32_t bufKh = bufb, bufKl = bufb + KARR;
        uint32_t bufVh = bufb + 2 * KARR, bufVl = bufb + 3 * KARR;

        float sc[8][4];
#pragma unroll
        for (int jn = 0; jn < 8; jn++) {
#pragma unroll
            for (int e = 0; e < 4; e++) sc[jn][e] = 0.f;
            uint32_t kbase = ((jn * 8 + krow_loc) * LDA + khalf) * 2;
#pragma unroll
            for (int ks = 0; ks < 3; ks++) {
                uint32_t kh0, kh1, kl0, kl1;
                LDSM_X2(kh0, kh1, bufKh + kbase + ks * 32);
                LDSM_X2(kl0, kl1, bufKl + kbase + ks * 32);
                MMA16816(sc[jn], qh[ks][0], qh[ks][1], qh[ks][2], qh[ks][3], kh0, kh1);
                MMA16816(sc[jn], qh[ks][0], qh[ks][1], qh[ks][2], qh[ks][3], kl0, kl1);
                MMA16816(sc[jn], ql[ks][0], ql[ks][1], ql[ks][2], ql[ks][3], kh0, kh1);
            }
        }

        int k0 = j * 64;
        if (j >= 2 * qt) {
            int qg0 = q0 + w * 16 + g;
#pragma unroll
            for (int jn = 0; jn < 8; jn++) {
                int cix = k0 + jn * 8 + 2 * t4;
                if (qg0 < cix)     sc[jn][0] = -1e30f;
                if (qg0 < cix + 1) sc[jn][1] = -1e30f;
                if (qg0 + 8 < cix)     sc[jn][2] = -1e30f;
                if (qg0 + 8 < cix + 1) sc[jn][3] = -1e30f;
            }
        }

        float mx0 = -1e30f, mx1 = -1e30f;
#pragma unroll
        for (int jn = 0; jn < 8; jn++) {
            mx0 = fmaxf(mx0, fmaxf(sc[jn][0], sc[jn][1]));
            mx1 = fmaxf(mx1, fmaxf(sc[jn][2], sc[jn][3]));
        }
        mx0 = fmaxf(mx0, __shfl_xor_sync(0xffffffffu, mx0, 1));
        mx0 = fmaxf(mx0, __shfl_xor_sync(0xffffffffu, mx0, 2));
        mx1 = fmaxf(mx1, __shfl_xor_sync(0xffffffffu, mx1, 1));
        mx1 = fmaxf(mx1, __shfl_xor_sync(0xffffffffu, mx1, 2));
        float mn0 = fmaxf(m0, mx0), mn1 = fmaxf(m1, mx1);
        float al0 = ex2(m0 - mn0), al1 = ex2(m1 - mn1);
        m0 = mn0; m1 = mn1;
        float ps0 = 0.f, ps1 = 0.f;
#pragma unroll
        for (int jn = 0; jn < 8; jn++) {
            sc[jn][0] = ex2(sc[jn][0] - mn0);
            sc[jn][1] = ex2(sc[jn][1] - mn0);
            sc[jn][2] = ex2(sc[jn][2] - mn1);
            sc[jn][3] = ex2(sc[jn][3] - mn1);
            ps0 += sc[jn][0] + sc[jn][1];
            ps1 += sc[jn][2] + sc[jn][3];
        }
        ps0 += __shfl_xor_sync(0xffffffffu, ps0, 1);
        ps0 += __shfl_xor_sync(0xffffffffu, ps0, 2);
        ps1 += __shfl_xor_sync(0xffffffffu, ps1, 1);
        ps1 += __shfl_xor_sync(0xffffffffu, ps1, 2);
        l0 = l0 * al0 + ps0;
        l1 = l1 * al1 + ps1;

#pragma unroll
        for (int on = 0; on < 6; on++) {
            o[on][0] *= al0; o[on][1] *= al0;
            o[on][2] *= al1; o[on][3] *= al1;
        }
#pragma unroll
        for (int ks = 0; ks < 4; ks++) {
            uint32_t pa[4], pl[4];
            pa[0] = pack_split(sc[2*ks][0],   sc[2*ks][1],   pl[0]);
            pa[1] = pack_split(sc[2*ks][2],   sc[2*ks][3],   pl[1]);
            pa[2] = pack_split(sc[2*ks+1][0], sc[2*ks+1][1], pl[2]);
            pa[3] = pack_split(sc[2*ks+1][2], sc[2*ks+1][3], pl[3]);
            uint32_t vrow = ((ks * 16 + krow_loc + khalf) * LDA) * 2;
#pragma unroll
            for (int on = 0; on < 6; on++) {
                uint32_t vh0, vh1, vl0, vl1;
                LDSM_X2T(vh0, vh1, bufVh + vrow + on * 16);
                LDSM_X2T(vl0, vl1, bufVl + vrow + on * 16);
                MMA16816(o[on], pa[0], pa[1], pa[2], pa[3], vh0, vh1);
                MMA16816(o[on], pa[0], pa[1], pa[2], pa[3], vl0, vl1);
                MMA16816(o[on], pl[0], pl[1], pl[2], pl[3], vh0, vh1);
            }
        }
        __syncthreads();
    }

    float inv0 = 1.f / l0, inv1 = 1.f / l1;
    float* op0 = Og + (size_t)(rowbase + q0 + w * 16 + g) * Dm + hoff + 2 * t4;
    float* op1 = op0 + 8 * Dm;
#pragma unroll
    for (int on = 0; on < 6; on++) {
        float2 r0 = make_float2(o[on][0] * inv0, o[on][1] * inv0);
        float2 r1 = make_float2(o[on][2] * inv1, o[on][3] * inv1);
        *(float2*)(op0 + on * 8) = r0;
        *(float2*)(op1 + on * 8) = r1;
    }
}

// ---------------------------------------------------------------------------
// LayerNorm: 192 threads/row, float4 per thread.
// ---------------------------------------------------------------------------
__global__ __launch_bounds__(192) void ln_kernel(
    const float* __restrict__ X, const float* __restrict__ gamma,
    const float* __restrict__ beta, float* __restrict__ Y)
{
    int row = blockIdx.x;
    int tid = threadIdx.x;
    const float* x = X + (size_t)row * Dm;

    float4 v = *(const float4*)(x + tid * 4);
    float s  = v.x + v.y + v.z + v.w;
    float sq = v.x * v.x + v.y * v.y + v.z * v.z + v.w * v.w;

#pragma unroll
    for (int off = 16; off > 0; off >>= 1) {
        s  += __shfl_xor_sync(0xffffffffu, s, off);
        sq += __shfl_xor_sync(0xffffffffu, sq, off);
    }
    __shared__ float red_s[6], red_q[6];
    int wid = tid >> 5, lid = tid & 31;
    if (lid == 0) { red_s[wid] = s; red_q[wid] = sq; }
    __syncthreads();
    float ts = 0.f, tq = 0.f;
#pragma unroll
    for (int i = 0; i < 6; i++) { ts += red_s[i]; tq += red_q[i]; }
    float mu  = ts * (1.f / Dm);
    float var = tq * (1.f / Dm) - mu * mu;
    float inv = rsqrtf(var + 1e-3f);

    float4 gmv = *(const float4*)(gamma + tid * 4);
    float4 btv = *(const float4*)(beta + tid * 4);
    float4 yv;
    yv.x = (v.x - mu) * inv * gmv.x + btv.x;
    yv.y = (v.y - mu) * inv * gmv.y + btv.y;
    yv.z = (v.z - mu) * inv * gmv.z + btv.z;
    yv.w = (v.w - mu) * inv * gmv.w + btv.w;
    *(float4*)(Y + (size_t)row * Dm + tid * 4) = yv;
}

// ---------------------------------------------------------------------------
extern "C" void kernel_launch(void* const* d_in, const int* in_sizes, int n_in,
                              void* d_out, int out_size)
{
    const float* q     = (const float*)d_in[0];
    const float* k     = (const float*)d_in[1];
    const float* v     = (const float*)d_in[2];
    const float* Wq    = (const float*)d_in[3];
    const float* bq    = (const float*)d_in[4];
    const float* Wk    = (const float*)d_in[5];
    const float* bk    = (const float*)d_in[6];
    const float* Wv    = (const float*)d_in[7];
    const float* bv    = (const float*)d_in[8];
    const float* gamma = (const float*)d_in[9];
    const float* beta  = (const float*)d_in[10];
    float* out = (float*)d_out;

    float* Og;
    __nv_bfloat16 *xhi, *xlo, *whi, *wlo;
    __nv_bfloat16 *qhi, *qlo, *khi, *klo, *vhi, *vlo;
    cudaGetSymbolAddress((void**)&Og, g_O);
    cudaGetSymbolAddress((void**)&xhi, g_Xhi);
    cudaGetSymbolAddress((void**)&xlo, g_Xlo);
    cudaGetSymbolAddress((void**)&whi, g_Wthi);
    cudaGetSymbolAddress((void**)&wlo, g_Wtlo);
    cudaGetSymbolAddress((void**)&qhi, g_Qhi);
    cudaGetSymbolAddress((void**)&qlo, g_Qlo);
    cudaGetSymbolAddress((void**)&khi, g_Khi);
    cudaGetSymbolAddress((void**)&klo, g_Klo);
    cudaGetSymbolAddress((void**)&vhi, g_Vhi);
    cudaGetSymbolAddress((void**)&vlo, g_Vlo);

    cudaFuncSetAttribute(gemm_mma_kernel, cudaFuncAttributeMaxDynamicSharedMemorySize,
                         GEMM_SMEM_BYTES);
    cudaFuncSetAttribute(attn_reg_kernel, cudaFuncAttributeMaxDynamicSharedMemorySize,
                         ATTN_SMEM);

    convert_x_kernel<<<dim3(NROWS * Dm / (256 * 4), 3), 256>>>(q, k, v, xhi, xlo);
    convert_w_kernel<<<dim3(Dm / 32, Dm / 32, 3), dim3(32, 8)>>>(Wq, Wk, Wv, whi, wlo);

    gemm_mma_kernel<<<dim3(Dm / 128, NROWS / 128, 3), 256, GEMM_SMEM_BYTES>>>(
        xhi, xlo, whi, wlo, bq, bk, bv, qhi, qlo, khi, klo, vhi, vlo);

    attn_reg_kernel<<<dim3(Sseq / 128, Bsz * Hh), 256, ATTN_SMEM>>>(
        qhi, qlo, khi, klo, vhi, vlo, Og);

    ln_kernel<<<NROWS, 192>>>(Og, gamma, beta, out);
}

// round 9
// speedup vs baseline: 3.0315x; 1.0207x over previous
#include <cuda_runtime.h>
#include <cuda_bf16.h>
#include <math.h>
#include <stdint.h>

#define Bsz   4
#define Sseq  2048
#define Dm    768
#define Hh    16
#define DHh   48
#define NROWS (Bsz * Sseq)
#define XELEMS ((size_t)NROWS * Dm)
#define WELEMS ((size_t)Dm * Dm)

// softmax scale (1/sqrt(48)) * log2(e): folded into Q projection; exp2 in softmax
#define QSCALE 0.2082351f

// Scratch (__device__ globals per allocation-free rule)
__device__ float g_O[NROWS * Dm];
__device__ __nv_bfloat16 g_Xhi[3 * XELEMS];
__device__ __nv_bfloat16 g_Xlo[3 * XELEMS];
__device__ __nv_bfloat16 g_Wthi[3 * WELEMS];
__device__ __nv_bfloat16 g_Wtlo[3 * WELEMS];
__device__ __nv_bfloat16 g_Qhi[XELEMS];
__device__ __nv_bfloat16 g_Qlo[XELEMS];
__device__ __nv_bfloat16 g_Khi[XELEMS];
__device__ __nv_bfloat16 g_Klo[XELEMS];
__device__ __nv_bfloat16 g_Vhi[XELEMS];
__device__ __nv_bfloat16 g_Vlo[XELEMS];

// ============================ PTX helpers ==================================
__device__ __forceinline__ uint32_t smem_u32(const void* p) {
    uint32_t a;
    asm("{ .reg .u64 t; cvta.to.shared.u64 t, %1; cvt.u32.u64 %0, t; }" : "=r"(a) : "l"(p));
    return a;
}
__device__ __forceinline__ float ex2(float x) {
    float y; asm("ex2.approx.ftz.f32 %0, %1;" : "=f"(y) : "f"(x)); return y;
}
#define MMA16816(C, a0, a1, a2, a3, b0, b1)                                   \
    asm volatile("mma.sync.aligned.m16n8k16.row.col.f32.bf16.bf16.f32 "       \
        "{%0,%1,%2,%3}, {%4,%5,%6,%7}, {%8,%9}, {%0,%1,%2,%3};"               \
        : "+f"((C)[0]), "+f"((C)[1]), "+f"((C)[2]), "+f"((C)[3])              \
        : "r"(a0), "r"(a1), "r"(a2), "r"(a3), "r"(b0), "r"(b1))
#define LDSM_X4(r0, r1, r2, r3, addr)                                         \
    asm volatile("ldmatrix.sync.aligned.m8n8.x4.shared.b16 {%0,%1,%2,%3}, [%4];" \
        : "=r"(r0), "=r"(r1), "=r"(r2), "=r"(r3) : "r"(addr))
#define LDSM_X2(r0, r1, addr)                                                 \
    asm volatile("ldmatrix.sync.aligned.m8n8.x2.shared.b16 {%0,%1}, [%2];"    \
        : "=r"(r0), "=r"(r1) : "r"(addr))
#define LDSM_X2T(r0, r1, addr)                                                \
    asm volatile("ldmatrix.sync.aligned.m8n8.x2.trans.shared.b16 {%0,%1}, [%2];" \
        : "=r"(r0), "=r"(r1) : "r"(addr))
#define CP_ASYNC16(sa, ga)                                                    \
    asm volatile("cp.async.cg.shared.global [%0], [%1], 16;" :: "r"(sa), "l"(ga))
#define CP_COMMIT() asm volatile("cp.async.commit_group;" ::: "memory")
#define CP_WAIT1()  asm volatile("cp.async.wait_group 1;" ::: "memory")
#define CP_WAIT0()  asm volatile("cp.async.wait_group 0;" ::: "memory")

// Cheap split: hi = mantissa-truncated bf16 pair via PRMT; lo = exact residual,
// rounded by one packed cvt. Trunc (vs RN) only doubles the dropped-term error.
__device__ __forceinline__ uint32_t pack_split2(float x, float y, uint32_t& lo) {
    uint32_t xb = __float_as_uint(x), yb = __float_as_uint(y);
    uint32_t hi;
    asm("prmt.b32 %0, %1, %2, 0x7632;" : "=r"(hi) : "r"(xb), "r"(yb));
    float xl = x - __uint_as_float(xb & 0xFFFF0000u);
    float yl = y - __uint_as_float(yb & 0xFFFF0000u);
    asm("cvt.rn.bf16x2.f32 %0, %1, %2;" : "=r"(lo) : "f"(yl), "f"(xl));
    return hi;
}

// ============================ converters (batched) =========================
__global__ __launch_bounds__(256) void convert_x_kernel(
    const float* __restrict__ q, const float* __restrict__ k,
    const float* __restrict__ v,
    __nv_bfloat16* __restrict__ hi, __nv_bfloat16* __restrict__ lo)
{
    int z = blockIdx.y;
    const float* X = (z == 0) ? q : (z == 1) ? k : v;
    size_t base = (size_t)z * XELEMS;
    size_t idx = ((size_t)blockIdx.x * 256 + threadIdx.x) * 4;
    float4 val = *(const float4*)(X + idx);
    __nv_bfloat16 h0 = __float2bfloat16_rn(val.x);
    __nv_bfloat16 h1 = __float2bfloat16_rn(val.y);
    __nv_bfloat16 h2 = __float2bfloat16_rn(val.z);
    __nv_bfloat16 h3 = __float2bfloat16_rn(val.w);
    __nv_bfloat16 l0 = __float2bfloat16_rn(val.x - __bfloat162float(h0));
    __nv_bfloat16 l1 = __float2bfloat16_rn(val.y - __bfloat162float(h1));
    __nv_bfloat16 l2 = __float2bfloat16_rn(val.z - __bfloat162float(h2));
    __nv_bfloat16 l3 = __float2bfloat16_rn(val.w - __bfloat162float(h3));
    __nv_bfloat162 hp0 = __nv_bfloat162(h0, h1), hp1 = __nv_bfloat162(h2, h3);
    __nv_bfloat162 lp0 = __nv_bfloat162(l0, l1), lp1 = __nv_bfloat162(l2, l3);
    uint2 hu, lu;
    hu.x = *(uint32_t*)&hp0; hu.y = *(uint32_t*)&hp1;
    lu.x = *(uint32_t*)&lp0; lu.y = *(uint32_t*)&lp1;
    *(uint2*)(hi + base + idx) = hu;
    *(uint2*)(lo + base + idx) = lu;
}

__global__ __launch_bounds__(256) void convert_w_kernel(
    const float* __restrict__ wq, const float* __restrict__ wk,
    const float* __restrict__ wv,
    __nv_bfloat16* __restrict__ hi, __nv_bfloat16* __restrict__ lo)
{
    __shared__ float tile[32][33];
    int z = blockIdx.z;
    const float* W = (z == 0) ? wq : (z == 1) ? wk : wv;
    size_t base = (size_t)z * WELEMS;
    int tx = threadIdx.x, ty = threadIdx.y;
    int bx = blockIdx.x, by = blockIdx.y;
#pragma unroll
    for (int i = 0; i < 4; i++) {
        int kk = by * 32 + ty + i * 8;
        int n = bx * 32 + tx;
        tile[ty + i * 8][tx] = W[kk * Dm + n];
    }
    __syncthreads();
#pragma unroll
    for (int i = 0; i < 4; i++) {
        int n = bx * 32 + ty + i * 8;
        int kk = by * 32 + tx;
        float v = tile[tx][ty + i * 8];
        __nv_bfloat16 h = __float2bfloat16_rn(v);
        __nv_bfloat16 l = __float2bfloat16_rn(v - __bfloat162float(h));
        hi[base + n * Dm + kk] = h;
        lo[base + n * Dm + kk] = l;
    }
}

// ======================= batched mma.sync GEMM (split-3) ===================
// CTA tile 128(M) x 64(N), BK=32, 2 CTAs/SM. Warp tile 32x32 (8 warps 4x2).
#define GLDA   40
#define GAPART (128 * GLDA * 2)               // 10240 B
#define GBPART (64 * GLDA * 2)                // 5120 B
#define GBUF   (2 * GAPART + 2 * GBPART)      // 30720 B
#define GEMM_SMEM_BYTES (2 * GBUF)            // 61440 B
#define GNCHK  (Dm / 32)                      // 24

__global__ __launch_bounds__(256, 2) void gemm_mma_kernel(
    const __nv_bfloat16* __restrict__ xhi, const __nv_bfloat16* __restrict__ xlo,
    const __nv_bfloat16* __restrict__ whi, const __nv_bfloat16* __restrict__ wlo,
    const float* __restrict__ bq, const float* __restrict__ bk,
    const float* __restrict__ bv,
    __nv_bfloat16* __restrict__ qhi, __nv_bfloat16* __restrict__ qlo,
    __nv_bfloat16* __restrict__ khi, __nv_bfloat16* __restrict__ klo,
    __nv_bfloat16* __restrict__ vhi, __nv_bfloat16* __restrict__ vlo)
{
    extern __shared__ __align__(128) char smraw[];
    uint32_t smb = smem_u32(smraw);
    int z = blockIdx.z;
    const __nv_bfloat16* Ahi = xhi + (size_t)z * XELEMS;
    const __nv_bfloat16* Alo = xlo + (size_t)z * XELEMS;
    const __nv_bfloat16* Bhi = whi + (size_t)z * WELEMS;
    const __nv_bfloat16* Blo = wlo + (size_t)z * WELEMS;
    const float* bias = (z == 0) ? bq : (z == 1) ? bk : bv;
    __nv_bfloat16* Yhi = (z == 0) ? qhi : (z == 1) ? khi : vhi;
    __nv_bfloat16* Ylo = (z == 0) ? qlo : (z == 1) ? klo : vlo;
    float scale = (z == 0) ? QSCALE : 1.0f;

    int tid = threadIdx.x;
    int w = tid >> 5, lane = tid & 31;
    int bm = blockIdx.y * 128;
    int bn = blockIdx.x * 64;

    int wm = (w >> 1) * 32;          // 0,32,64,96
    int wn = (w & 1) * 32;           // 0,32

    int mat = lane >> 3;
    int arow = ((mat & 1) << 3) + (lane & 7);
    int acol8 = (mat >> 1) << 3;
    int brow = ((mat >> 1) << 3) + (lane & 7);
    int bcol8 = (mat & 1) << 3;

    float c[2][4][4];
#pragma unroll
    for (int mf = 0; mf < 2; mf++)
#pragma unroll
        for (int nf = 0; nf < 4; nf++)
#pragma unroll
            for (int e = 0; e < 4; e++) c[mf][nf][e] = 0.f;

// 1536 x 16B per chunk = 6 per thread.
#define GEMM_ISSUE(c0, bufsel) do {                                           \
    int k0_ = (c0) * 32;                                                      \
    uint32_t bb_ = smb + (bufsel) * GBUF;                                     \
    _Pragma("unroll")                                                         \
    for (int it = 0; it < 6; it++) {                                          \
        int idx = tid + it * 256;                                             \
        const __nv_bfloat16* ga; uint32_t sa;                                 \
        if (idx < 1024) {                                                     \
            int part = idx >> 9, rem = idx & 511;                             \
            int row = rem >> 2, seg = rem & 3;                                \
            ga = (part ? Alo : Ahi) + (size_t)(bm + row) * Dm + k0_ + seg * 8;\
            sa = bb_ + part * GAPART + row * (GLDA * 2) + seg * 16;           \
        } else {                                                              \
            int t = idx - 1024;                                               \
            int part = t >> 8, rem = t & 255;                                 \
            int row = rem >> 2, seg = rem & 3;                                \
            ga = (part ? Blo : Bhi) + (size_t)(bn + row) * Dm + k0_ + seg * 8;\
            sa = bb_ + 2 * GAPART + part * GBPART + row * (GLDA * 2) + seg * 16; \
        }                                                                     \
        CP_ASYNC16(sa, ga);                                                   \
    }                                                                         \
    CP_COMMIT();                                                              \
} while (0)

    GEMM_ISSUE(0, 0);

    for (int cc = 0; cc < GNCHK; cc++) {
        int buf = cc & 1;
        if (cc + 1 < GNCHK) {
            GEMM_ISSUE(cc + 1, buf ^ 1);
            CP_WAIT1();
        } else {
            CP_WAIT0();
        }
        __syncthreads();

        uint32_t bb = smb + buf * GBUF;
        uint32_t sAh = bb, sAl = bb + GAPART;
        uint32_t sBh = bb + 2 * GAPART, sBl = bb + 2 * GAPART + GBPART;

#pragma unroll
        for (int ks = 0; ks < 2; ks++) {
            uint32_t ah[2][4], al[2][4];
#pragma unroll
            for (int mf = 0; mf < 2; mf++) {
                uint32_t a = ((wm + mf * 16 + arow) * GLDA + ks * 16 + acol8) * 2;
                LDSM_X4(ah[mf][0], ah[mf][1], ah[mf][2], ah[mf][3], sAh + a);
                LDSM_X4(al[mf][0], al[mf][1], al[mf][2], al[mf][3], sAl + a);
            }
            uint32_t bh[4][2], bl[4][2];
#pragma unroll
            for (int nf2 = 0; nf2 < 2; nf2++) {
                uint32_t a = ((wn + nf2 * 16 + brow) * GLDA + ks * 16 + bcol8) * 2;
                uint32_t r0, r1, r2, r3;
                LDSM_X4(r0, r1, r2, r3, sBh + a);
                bh[nf2 * 2][0] = r0; bh[nf2 * 2][1] = r1;
                bh[nf2 * 2 + 1][0] = r2; bh[nf2 * 2 + 1][1] = r3;
                LDSM_X4(r0, r1, r2, r3, sBl + a);
                bl[nf2 * 2][0] = r0; bl[nf2 * 2][1] = r1;
                bl[nf2 * 2 + 1][0] = r2; bl[nf2 * 2 + 1][1] = r3;
            }
#pragma unroll
            for (int mf = 0; mf < 2; mf++)
#pragma unroll
                for (int nf = 0; nf < 4; nf++) {
                    MMA16816(c[mf][nf], ah[mf][0], ah[mf][1], ah[mf][2], ah[mf][3],
                             bh[nf][0], bh[nf][1]);
                    MMA16816(c[mf][nf], ah[mf][0], ah[mf][1], ah[mf][2], ah[mf][3],
                             bl[nf][0], bl[nf][1]);
                    MMA16816(c[mf][nf], al[mf][0], al[mf][1], al[mf][2], al[mf][3],
                             bh[nf][0], bh[nf][1]);
                }
        }
        __syncthreads();
    }

    // Epilogue: stage f32 (128x64 = 32 KB) into smem, then coalesced split out
    float* sOut = (float*)smraw;
    int g = lane >> 2, t4 = lane & 3;
#pragma unroll
    for (int mf = 0; mf < 2; mf++) {
        int m0 = wm + mf * 16 + g;
#pragma unroll
        for (int nf = 0; nf < 4; nf++) {
            int col = wn + nf * 8 + t4 * 2;
            sOut[m0 * 64 + col]       = c[mf][nf][0];
            sOut[m0 * 64 + col + 1]   = c[mf][nf][1];
            sOut[(m0 + 8) * 64 + col]     = c[mf][nf][2];
            sOut[(m0 + 8) * 64 + col + 1] = c[mf][nf][3];
        }
    }
    __syncthreads();

#pragma unroll
    for (int it = 0; it < 8; it++) {
        int idx = tid + it * 256;           // 2048 float4 slots (128 x 16)
        int row = idx >> 4, c4 = (idx & 15) * 4;
        float4 o = *(float4*)(sOut + row * 64 + c4);
        const float* bp = bias + bn + c4;
        float y0 = (o.x + bp[0]) * scale;
        float y1 = (o.y + bp[1]) * scale;
        float y2 = (o.z + bp[2]) * scale;
        float y3 = (o.w + bp[3]) * scale;
        uint32_t l01, l23;
        uint32_t h01 = pack_split2(y0, y1, l01);
        uint32_t h23 = pack_split2(y2, y3, l23);
        uint2 hu = make_uint2(h01, h23);
        uint2 lu = make_uint2(l01, l23);
        size_t off = (size_t)(bm + row) * Dm + bn + c4;
        *(uint2*)(Yhi + off) = hu;
        *(uint2*)(Ylo + off) = lu;
    }
}

// ============== register-resident flash attention (mma.sync) ===============
#define LDA 56
#define QARR (128 * LDA * 2)
#define KARR (64 * LDA * 2)
#define BUFB (4 * KARR)
#define ATTN_SMEM (2 * QARR + 3 * BUFB)

__global__ __launch_bounds__(256, 2) void attn_reg_kernel(
    const __nv_bfloat16* __restrict__ Qh_g, const __nv_bfloat16* __restrict__ Ql_g,
    const __nv_bfloat16* __restrict__ Kh_g, const __nv_bfloat16* __restrict__ Kl_g,
    const __nv_bfloat16* __restrict__ Vh_g, const __nv_bfloat16* __restrict__ Vl_g,
    float* __restrict__ Og)
{
    extern __shared__ __align__(128) char smraw[];
    uint32_t smb = smem_u32(smraw);
    __nv_bfloat16* Qh = (__nv_bfloat16*)smraw;
    __nv_bfloat16* Ql = (__nv_bfloat16*)(smraw + QARR);

    int qt = (int)gridDim.x - 1 - (int)blockIdx.x;
    int bh = blockIdx.y;
    int b = bh >> 4, h = bh & 15;
    int tid = threadIdx.x;
    int w = tid >> 5, lane = tid & 31;
    int rowbase = b * Sseq;
    int q0 = qt * 128;
    int hoff = h * DHh;
    int ntiles = 2 * qt + 2;

    {
#pragma unroll
        for (int it = 0; it < 6; it++) {
            int s = tid + it * 256;
            int arr = s / 384, rem = s - arr * 384;
            int r = rem / 6, c16 = rem - r * 6;
            const __nv_bfloat16* src = (arr == 0) ? Kh_g : (arr == 1) ? Kl_g :
                                       (arr == 2) ? Vh_g : Vl_g;
            const __nv_bfloat16* ga = src + (size_t)(rowbase + r) * Dm + hoff + c16 * 8;
            uint32_t sa = smb + 2 * QARR + arr * KARR + r * (LDA * 2) + c16 * 16;
            CP_ASYNC16(sa, ga);
        }
        CP_COMMIT();
    }

    for (int s = tid; s < 1536; s += 256) {
        int arr = s / 768;
        int rem = s - arr * 768;
        int r = rem / 6, c8 = (rem - r * 6) * 8;
        const __nv_bfloat16* src = (arr ? Ql_g : Qh_g) +
            (size_t)(rowbase + q0 + r) * Dm + hoff + c8;
        __nv_bfloat16* dst = (arr ? Ql : Qh) + r * LDA + c8;
        *(uint4*)dst = *(const uint4*)src;
    }
    __syncthreads();

    int mat = lane >> 3;
    int qrow_loc = ((mat & 1) << 3) + (lane & 7);
    int qcol8 = (mat >> 1) << 3;
    uint32_t qh[3][4], ql[3][4];
#pragma unroll
    for (int ks = 0; ks < 3; ks++) {
        uint32_t a = smb + ((w * 16 + qrow_loc) * LDA + ks * 16 + qcol8) * 2;
        LDSM_X4(qh[ks][0], qh[ks][1], qh[ks][2], qh[ks][3], a);
        LDSM_X4(ql[ks][0], ql[ks][1], ql[ks][2], ql[ks][3], a + QARR);
    }

    int g = lane >> 2, t4 = lane & 3;
    int lane16 = lane & 15;
    int krow_loc = lane16 & 7;
    int khalf = (lane16 >> 3) << 3;

    float m0 = -1e30f, m1 = -1e30f, l0 = 0.f, l1 = 0.f;
    float o[6][4];
#pragma unroll
    for (int on = 0; on < 6; on++)
#pragma unroll
        for (int e = 0; e < 4; e++) o[on][e] = 0.f;

    for (int j = 0; j < ntiles; j++) {
        if (j + 1 < ntiles) {
            int k0n = (j + 1) * 64;
            uint32_t bb = smb + 2 * QARR + ((j + 1) % 3) * BUFB;
#pragma unroll
            for (int it = 0; it < 6; it++) {
                int s = tid + it * 256;
                int arr = s / 384, rem = s - arr * 384;
                int r = rem / 6, c16 = rem - r * 6;
                const __nv_bfloat16* src = (arr == 0) ? Kh_g : (arr == 1) ? Kl_g :
                                           (arr == 2) ? Vh_g : Vl_g;
                const __nv_bfloat16* ga = src + (size_t)(rowbase + k0n + r) * Dm + hoff + c16 * 8;
                uint32_t sa = bb + arr * KARR + r * (LDA * 2) + c16 * 16;
                CP_ASYNC16(sa, ga);
            }
            CP_COMMIT();
            CP_WAIT1();
        } else {
            CP_WAIT0();
        }
        __syncthreads();

        uint32_t bufb = smb + 2 * QARR + (j % 3) * BUFB;
        uint32_t bufKh = bufb, bufKl = bufb + KARR;
        uint32_t bufVh = bufb + 2 * KARR, bufVl = bufb + 3 * KARR;

        float sc[8][4];
#pragma unroll
        for (int jn = 0; jn < 8; jn++) {
#pragma unroll
            for (int e = 0; e < 4; e++) sc[jn][e] = 0.f;
            uint32_t kbase = ((jn * 8 + krow_loc) * LDA + khalf) * 2;
#pragma unroll
            for (int ks = 0; ks < 3; ks++) {
                uint32_t kh0, kh1, kl0, kl1;
                LDSM_X2(kh0, kh1, bufKh + kbase + ks * 32);
                LDSM_X2(kl0, kl1, bufKl + kbase + ks * 32);
                MMA16816(sc[jn], qh[ks][0], qh[ks][1], qh[ks][2], qh[ks][3], kh0, kh1);
                MMA16816(sc[jn], qh[ks][0], qh[ks][1], qh[ks][2], qh[ks][3], kl0, kl1);
                MMA16816(sc[jn], ql[ks][0], ql[ks][1], ql[ks][2], ql[ks][3], kh0, kh1);
            }
        }

        int k0 = j * 64;
        if (j >= 2 * qt) {
            int qg0 = q0 + w * 16 + g;
#pragma unroll
            for (int jn = 0; jn < 8; jn++) {
                int cix = k0 + jn * 8 + 2 * t4;
                if (qg0 < cix)     sc[jn][0] = -1e30f;
                if (qg0 < cix + 1) sc[jn][1] = -1e30f;
                if (qg0 + 8 < cix)     sc[jn][2] = -1e30f;
                if (qg0 + 8 < cix + 1) sc[jn][3] = -1e30f;
            }
        }

        float mx0 = -1e30f, mx1 = -1e30f;
#pragma unroll
        for (int jn = 0; jn < 8; jn++) {
            mx0 = fmaxf(mx0, fmaxf(sc[jn][0], sc[jn][1]));
            mx1 = fmaxf(mx1, fmaxf(sc[jn][2], sc[jn][3]));
        }
        mx0 = fmaxf(mx0, __shfl_xor_sync(0xffffffffu, mx0, 1));
        mx0 = fmaxf(mx0, __shfl_xor_sync(0xffffffffu, mx0, 2));
        mx1 = fmaxf(mx1, __shfl_xor_sync(0xffffffffu, mx1, 1));
        mx1 = fmaxf(mx1, __shfl_xor_sync(0xffffffffu, mx1, 2));
        float mn0 = fmaxf(m0, mx0), mn1 = fmaxf(m1, mx1);
        float al0 = ex2(m0 - mn0), al1 = ex2(m1 - mn1);
        m0 = mn0; m1 = mn1;
        float ps0 = 0.f, ps1 = 0.f;
#pragma unroll
        for (int jn = 0; jn < 8; jn++) {
            sc[jn][0] = ex2(sc[jn][0] - mn0);
            sc[jn][1] = ex2(sc[jn][1] - mn0);
            sc[jn][2] = ex2(sc[jn][2] - mn1);
            sc[jn][3] = ex2(sc[jn][3] - mn1);
            ps0 += sc[jn][0] + sc[jn][1];
            ps1 += sc[jn][2] + sc[jn][3];
        }
        ps0 += __shfl_xor_sync(0xffffffffu, ps0, 1);
        ps0 += __shfl_xor_sync(0xffffffffu, ps0, 2);
        ps1 += __shfl_xor_sync(0xffffffffu, ps1, 1);
        ps1 += __shfl_xor_sync(0xffffffffu, ps1, 2);
        l0 = l0 * al0 + ps0;
        l1 = l1 * al1 + ps1;

#pragma unroll
        for (int on = 0; on < 6; on++) {
            o[on][0] *= al0; o[on][1] *= al0;
            o[on][2] *= al1; o[on][3] *= al1;
        }
#pragma unroll
        for (int ks = 0; ks < 4; ks++) {
            uint32_t pa[4], pl[4];
            pa[0] = pack_split2(sc[2*ks][0],   sc[2*ks][1],   pl[0]);
            pa[1] = pack_split2(sc[2*ks][2],   sc[2*ks][3],   pl[1]);
            pa[2] = pack_split2(sc[2*ks+1][0], sc[2*ks+1][1], pl[2]);
            pa[3] = pack_split2(sc[2*ks+1][2], sc[2*ks+1][3], pl[3]);
            uint32_t vrow = ((ks * 16 + krow_loc + khalf) * LDA) * 2;
#pragma unroll
            for (int on = 0; on < 6; on++) {
                uint32_t vh0, vh1, vl0, vl1;
                LDSM_X2T(vh0, vh1, bufVh + vrow + on * 16);
                LDSM_X2T(vl0, vl1, bufVl + vrow + on * 16);
                MMA16816(o[on], pa[0], pa[1], pa[2], pa[3], vh0, vh1);
                MMA16816(o[on], pa[0], pa[1], pa[2], pa[3], vl0, vl1);
                MMA16816(o[on], pl[0], pl[1], pl[2], pl[3], vh0, vh1);
            }
        }
        __syncthreads();
    }

    float inv0 = 1.f / l0, inv1 = 1.f / l1;
    float* op0 = Og + (size_t)(rowbase + q0 + w * 16 + g) * Dm + hoff + 2 * t4;
    float* op1 = op0 + 8 * Dm;
#pragma unroll
    for (int on = 0; on < 6; on++) {
        float2 r0 = make_float2(o[on][0] * inv0, o[on][1] * inv0);
        float2 r1 = make_float2(o[on][2] * inv1, o[on][3] * inv1);
        *(float2*)(op0 + on * 8) = r0;
        *(float2*)(op1 + on * 8) = r1;
    }
}

// ---------------------------------------------------------------------------
// LayerNorm: 192 threads/row, float4 per thread.
// ---------------------------------------------------------------------------
__global__ __launch_bounds__(192) void ln_kernel(
    const float* __restrict__ X, const float* __restrict__ gamma,
    const float* __restrict__ beta, float* __restrict__ Y)
{
    int row = blockIdx.x;
    int tid = threadIdx.x;
    const float* x = X + (size_t)row * Dm;

    float4 v = *(const float4*)(x + tid * 4);
    float s  = v.x + v.y + v.z + v.w;
    float sq = v.x * v.x + v.y * v.y + v.z * v.z + v.w * v.w;

#pragma unroll
    for (int off = 16; off > 0; off >>= 1) {
        s  += __shfl_xor_sync(0xffffffffu, s, off);
        sq += __shfl_xor_sync(0xffffffffu, sq, off);
    }
    __shared__ float red_s[6], red_q[6];
    int wid = tid >> 5, lid = tid & 31;
    if (lid == 0) { red_s[wid] = s; red_q[wid] = sq; }
    __syncthreads();
    float ts = 0.f, tq = 0.f;
#pragma unroll
    for (int i = 0; i < 6; i++) { ts += red_s[i]; tq += red_q[i]; }
    float mu  = ts * (1.f / Dm);
    float var = tq * (1.f / Dm) - mu * mu;
    float inv = rsqrtf(var + 1e-3f);

    float4 gmv = *(const float4*)(gamma + tid * 4);
    float4 btv = *(const float4*)(beta + tid * 4);
    float4 yv;
    yv.x = (v.x - mu) * inv * gmv.x + btv.x;
    yv.y = (v.y - mu) * inv * gmv.y + btv.y;
    yv.z = (v.z - mu) * inv * gmv.z + btv.z;
    yv.w = (v.w - mu) * inv * gmv.w + btv.w;
    *(float4*)(Y + (size_t)row * Dm + tid * 4) = yv;
}

// ---------------------------------------------------------------------------
extern "C" void kernel_launch(void* const* d_in, const int* in_sizes, int n_in,
                              void* d_out, int out_size)
{
    const float* q     = (const float*)d_in[0];
    const float* k     = (const float*)d_in[1];
    const float* v     = (const float*)d_in[2];
    const float* Wq    = (const float*)d_in[3];
    const float* bq    = (const float*)d_in[4];
    const float* Wk    = (const float*)d_in[5];
    const float* bk    = (const float*)d_in[6];
    const float* Wv    = (const float*)d_in[7];
    const float* bv    = (const float*)d_in[8];
    const float* gamma = (const float*)d_in[9];
    const float* beta  = (const float*)d_in[10];
    float* out = (float*)d_out;

    float* Og;
    __nv_bfloat16 *xhi, *xlo, *whi, *wlo;
    __nv_bfloat16 *qhi, *qlo, *khi, *klo, *vhi, *vlo;
    cudaGetSymbolAddress((void**)&Og, g_O);
    cudaGetSymbolAddress((void**)&xhi, g_Xhi);
    cudaGetSymbolAddress((void**)&xlo, g_Xlo);
    cudaGetSymbolAddress((void**)&whi, g_Wthi);
    cudaGetSymbolAddress((void**)&wlo, g_Wtlo);
    cudaGetSymbolAddress((void**)&qhi, g_Qhi);
    cudaGetSymbolAddress((void**)&qlo, g_Qlo);
    cudaGetSymbolAddress((void**)&khi, g_Khi);
    cudaGetSymbolAddress((void**)&klo, g_Klo);
    cudaGetSymbolAddress((void**)&vhi, g_Vhi);
    cudaGetSymbolAddress((void**)&vlo, g_Vlo);

    cudaFuncSetAttribute(gemm_mma_kernel, cudaFuncAttributeMaxDynamicSharedMemorySize,
                         GEMM_SMEM_BYTES);
    cudaFuncSetAttribute(attn_reg_kernel, cudaFuncAttributeMaxDynamicSharedMemorySize,
                         ATTN_SMEM);

    convert_x_kernel<<<dim3(NROWS * Dm / (256 * 4), 3), 256>>>(q, k, v, xhi, xlo);
    convert_w_kernel<<<dim3(Dm / 32, Dm / 32, 3), dim3(32, 8)>>>(Wq, Wk, Wv, whi, wlo);

    gemm_mma_kernel<<<dim3(Dm / 64, NROWS / 128, 3), 256, GEMM_SMEM_BYTES>>>(
        xhi, xlo, whi, wlo, bq, bk, bv, qhi, qlo, khi, klo, vhi, vlo);

    attn_reg_kernel<<<dim3(Sseq / 128, Bsz * Hh), 256, ATTN_SMEM>>>(
        qhi, qlo, khi, klo, vhi, vlo, Og);

    ln_kernel<<<NROWS, 192>>>(Og, gamma, beta, out);
}